// round 12
// baseline (speedup 1.0000x reference)
#include <cuda_runtime.h>
#include <cuda_bf16.h>
#include <math.h>
#include <stdint.h>

// Problem constants
#define BATCH 8
#define SEQ   2048
#define DMODEL 512

#define BM 256
#define BN 128
// panel tile: 128 rows x 128B (hi [0,64), lo [64,128)), XOR-swizzled = 16KB
#define TILE_B  16384
#define STAGE_B (3 * TILE_B)          // A0 + A1 + B = 48KB
#define NSTAGE  4
#define DYN_SMEM (NSTAGE * STAGE_B)   // 192 KB

#define ICH 8                 // softmax i-chunks == SEQ/BM
#define MODE_PROJ   0
#define MODE_SCORES 1
#define MODE_AV     2

typedef __nv_bfloat16 bf16;
typedef __nv_bfloat162 bf162;

// ---------------------------------------------------------------------------
// Device scratch: panel (tile-major, pre-swizzled) arrays, hi+lo combined.
// ---------------------------------------------------------------------------
__device__ bf16 g_x[(long)BATCH * SEQ * DMODEL * 2];        // panels, KC=16
__device__ bf16 g_Wt[3L * DMODEL * DMODEL * 2];             // panels, KC=16
__device__ bf16 g_Q[(long)BATCH * SEQ * DMODEL * 2];        // panels, KC=16
__device__ bf16 g_K[(long)BATCH * SEQ * DMODEL * 2];        // panels, KC=16
__device__ bf16 g_Vhi[(long)BATCH * SEQ * DMODEL];          // linear
__device__ bf16 g_Vlo[(long)BATCH * SEQ * DMODEL];          // linear
__device__ bf16 g_Vt[(long)BATCH * DMODEL * SEQ * 2];       // panels, KC=64
__device__ bf16 g_W[(long)BATCH * SEQ * SEQ * 2];           // panels, KC=64
__device__ float g_pm[BATCH * ICH * SEQ], g_ps[BATCH * ICH * SEQ];
__device__ float g_gm[BATCH * SEQ], g_gi[BATCH * SEQ];

// Panel element addressing (within a 16KB tile)
__device__ __forceinline__ uint32_t off_hi(int r, int kk) {
    return (uint32_t)((r << 7) + ((((kk >> 3) << 4) ^ ((r & 7) << 4)) | ((kk & 7) << 1)));
}
__device__ __forceinline__ uint32_t off_lo(int r, int kk) {
    return (uint32_t)((r << 7) + (((((kk >> 3) + 4) << 4) ^ ((r & 7) << 4)) | ((kk & 7) << 1)));
}

// ---------------------------------------------------------------------------
// PTX helpers
// ---------------------------------------------------------------------------
__device__ __forceinline__ uint32_t smem_u32(const void* p) {
    uint32_t a;
    asm("{ .reg .u64 t; cvta.to.shared.u64 t, %1; cvt.u32.u64 %0, t; }"
        : "=r"(a) : "l"(p));
    return a;
}
__device__ __forceinline__ void ldm_x4(uint32_t* r, uint32_t addr) {
    asm volatile("ldmatrix.sync.aligned.m8n8.x4.shared.b16 {%0,%1,%2,%3}, [%4];"
        : "=r"(r[0]), "=r"(r[1]), "=r"(r[2]), "=r"(r[3]) : "r"(addr));
}
__device__ __forceinline__ void mma16816(float* c, const uint32_t* a, const uint32_t* b) {
    asm volatile(
        "mma.sync.aligned.m16n8k16.row.col.f32.bf16.bf16.f32 "
        "{%0,%1,%2,%3}, {%4,%5,%6,%7}, {%8,%9}, {%0,%1,%2,%3};"
        : "+f"(c[0]), "+f"(c[1]), "+f"(c[2]), "+f"(c[3])
        : "r"(a[0]), "r"(a[1]), "r"(a[2]), "r"(a[3]), "r"(b[0]), "r"(b[1]));
}

#define MBARRIER_INIT(addr, cnt) \
    asm volatile("mbarrier.init.shared.b64 [%0], %1;" \
                 :: "r"((uint32_t)(addr)), "r"((uint32_t)(cnt)) : "memory")
#define MBARRIER_EXPECT_TX(addr, bytes) \
    asm volatile("mbarrier.arrive.expect_tx.shared.b64 _, [%0], %1;" \
                 :: "r"((uint32_t)(addr)), "r"((uint32_t)(bytes)) : "memory")
#define CP_BULK(dst, src, bytes, bar) \
    asm volatile("cp.async.bulk.shared::cta.global.mbarrier::complete_tx::bytes " \
                 "[%0], [%1], %2, [%3];" \
                 :: "r"((uint32_t)(dst)), "l"(src), "r"((uint32_t)(bytes)), \
                    "r"((uint32_t)(bar)) : "memory")
#define FENCE_PROXY_ASYNC() \
    asm volatile("fence.proxy.async.shared::cta;" ::: "memory")

#define MBARRIER_WAIT_PARITY(mbar_smem_addr, phase_parity) do { \
    uint32_t _mbar = (uint32_t)(mbar_smem_addr); \
    uint32_t _parity = (uint32_t)(phase_parity); \
    uint32_t _done; \
    asm volatile( \
        "{\n\t.reg .pred p;\n\t" \
        "mbarrier.try_wait.parity.acquire.cta.shared::cta.b64 p, [%1], %2;\n\t" \
        "selp.b32 %0, 1, 0, p;\n\t}" \
        : "=r"(_done) : "r"(_mbar), "r"(_parity) : "memory"); \
    if (!_done) { \
        asm volatile( \
            "{\n\t.reg .pred P1;\n\t" \
            "WAIT_LOOP_%=:\n\t" \
            "mbarrier.try_wait.parity.acquire.cta.shared::cta.b64 P1, [%0], %1, 0x989680;\n\t" \
            "@P1 bra.uni WAIT_DONE_%=;\n\t" \
            "bra.uni WAIT_LOOP_%=;\n\t" \
            "WAIT_DONE_%=:\n\t}" \
            :: "r"(_mbar), "r"(_parity) : "memory"); \
    } \
} while(0)

// ===========================================================================
// GEMM on panel-layout split bf16, 3-term split (hh+hl+lh).
// CTA tile 256x128, 256 threads (4 warp_m x 2 warp_n, 64x64 warp tiles).
// Tiles fetched with cp.async.bulk (3 x 16KB / chunk) into a 4-stage ring.
// ===========================================================================
template<int MODE>
__global__ __launch_bounds__(256, 1)
void gemm_ps(const char* __restrict__ Ab, const char* __restrict__ Bb,
             float alpha, int N, int KC, long sA, long sB, long sC,
             float* __restrict__ Cf,
             float* __restrict__ pm, float* __restrict__ ps,
             const float* __restrict__ bq, const float* __restrict__ bk,
             const float* __restrict__ bv,
             bf16* __restrict__ Qp, bf16* __restrict__ Kp,
             bf16* __restrict__ Vhi, bf16* __restrict__ Vlo)
{
    const char* A = Ab + (long)blockIdx.z * sA;
    const char* B = Bb + (long)blockIdx.z * sB;
    const long zc = (long)blockIdx.z * sC;
    const int bm = blockIdx.y * BM;
    const int bn = blockIdx.x * BN;
    const int tid = threadIdx.x;
    const int wid = tid >> 5, lane = tid & 31;
    const int warp_m = wid & 3;    // 4 groups of 64 rows
    const int warp_n = wid >> 2;   // 2 groups of 64 cols

    extern __shared__ __align__(16) char dynsmem[];
    const uint32_t sbase = smem_u32(dynsmem);
    __shared__ __align__(8) unsigned long long s_bar[NSTAGE];
    const uint32_t bar0 = smem_u32(s_bar);

    if (tid == 0) {
        #pragma unroll
        for (int s = 0; s < NSTAGE; s++) MBARRIER_INIT(bar0 + s * 8, 1);
        FENCE_PROXY_ASYNC();
    }
    __syncthreads();

    float acc[4][8][4] = {};   // [mi][ni][frag]

    // ldmatrix lane-address components; A row panel chosen by warp_m>>1
    const int a_rowl = (warp_m & 1) * 64 + (lane & 15);
    const uint32_t a_pansel = (uint32_t)((warp_m >> 1) * TILE_B);
    const uint32_t a_k = (uint32_t)(((lane >> 4) * 8) * 2);
    const int b_row = warp_n * 64 + (lane & 7) + ((lane >> 4) * 8);
    const uint32_t b_k = (uint32_t)((((lane >> 3) & 1) * 8) * 2);
    const uint32_t swz = (uint32_t)((lane & 7) << 4);

    const int nch = KC;
    const long pA0 = (long)(blockIdx.y * 2) * KC;       // A panel row-block 0
    const long pA1 = pA0 + KC;                          // A panel row-block 1
    const long pB  = (long)blockIdx.x * KC;

    // Prologue: issue chunks 0..2 (3-chunk lead)
    if (tid == 0) {
        #pragma unroll
        for (int c = 0; c < 3; c++) {
            const uint32_t bar = bar0 + c * 8;
            const uint32_t dst = sbase + c * STAGE_B;
            MBARRIER_EXPECT_TX(bar, 3 * TILE_B);
            CP_BULK(dst,              A + ((pA0 + c) << 14), TILE_B, bar);
            CP_BULK(dst + TILE_B,     A + ((pA1 + c) << 14), TILE_B, bar);
            CP_BULK(dst + 2 * TILE_B, B + ((pB + c) << 14), TILE_B, bar);
        }
    }

    for (int c = 0; c < nch; c++) {
        // Issue chunk c+3 into stage (c+3)%4 (its readers finished at c-1)
        if (tid == 0 && c + 3 < nch) {
            const int s = (c + 3) % NSTAGE;
            const uint32_t bar = bar0 + s * 8;
            const uint32_t dst = sbase + s * STAGE_B;
            MBARRIER_EXPECT_TX(bar, 3 * TILE_B);
            CP_BULK(dst,              A + ((pA0 + c + 3) << 14), TILE_B, bar);
            CP_BULK(dst + TILE_B,     A + ((pA1 + c + 3) << 14), TILE_B, bar);
            CP_BULK(dst + 2 * TILE_B, B + ((pB + c + 3) << 14), TILE_B, bar);
        }

        const int st = c % NSTAGE;
        MBARRIER_WAIT_PARITY(bar0 + st * 8, (c / NSTAGE) & 1);

        const uint32_t uA = sbase + st * STAGE_B + a_pansel;
        const uint32_t uB = sbase + st * STAGE_B + 2 * TILE_B;

        #pragma unroll
        for (int ks = 0; ks < 2; ks++) {
            const uint32_t akh = ((a_k + ks * 32) ^ swz);
            const uint32_t akl = ((a_k + ks * 32 + 64) ^ swz);
            const uint32_t bkh = ((b_k + ks * 32) ^ swz);
            const uint32_t bkl = ((b_k + ks * 32 + 64) ^ swz);
            uint32_t afh[4][4], afl[4][4], bfh[4][4], bfl[4][4];
            #pragma unroll
            for (int mi = 0; mi < 4; mi++)
                ldm_x4(afh[mi], uA + (uint32_t)((a_rowl + mi * 16) * 128) + akh);
            #pragma unroll
            for (int nb2 = 0; nb2 < 4; nb2++)
                ldm_x4(bfh[nb2], uB + (uint32_t)((b_row + nb2 * 16) * 128) + bkh);
            #pragma unroll
            for (int mi = 0; mi < 4; mi++)
                #pragma unroll
                for (int ni = 0; ni < 8; ni++)
                    mma16816(acc[mi][ni], afh[mi], &bfh[ni >> 1][(ni & 1) * 2]);
            #pragma unroll
            for (int nb2 = 0; nb2 < 4; nb2++)
                ldm_x4(bfl[nb2], uB + (uint32_t)((b_row + nb2 * 16) * 128) + bkl);
            #pragma unroll
            for (int mi = 0; mi < 4; mi++)
                #pragma unroll
                for (int ni = 0; ni < 8; ni++)
                    mma16816(acc[mi][ni], afh[mi], &bfl[ni >> 1][(ni & 1) * 2]);
            #pragma unroll
            for (int mi = 0; mi < 4; mi++)
                ldm_x4(afl[mi], uA + (uint32_t)((a_rowl + mi * 16) * 128) + akl);
            #pragma unroll
            for (int mi = 0; mi < 4; mi++)
                #pragma unroll
                for (int ni = 0; ni < 8; ni++)
                    mma16816(acc[mi][ni], afl[mi], &bfh[ni >> 1][(ni & 1) * 2]);
        }
        __syncthreads();   // all readers done before stage is re-armed
    }

    // ---------------- Epilogue ----------------
    const int erow = lane >> 2;
    const int ecol = 2 * (lane & 3);

    if (MODE == MODE_PROJ) {
        #pragma unroll
        for (int mi = 0; mi < 4; mi++) {
            #pragma unroll
            for (int ni = 0; ni < 8; ni++) {
                const int col = bn + warp_n * 64 + ni * 8 + ecol;
                const int sel = col >> 9;
                const int nn = col & 511;
                const float* bp = (sel == 0) ? bq : (sel == 1) ? bk : bv;
                const float bx = bp[nn], by = bp[nn + 1];
                #pragma unroll
                for (int h = 0; h < 2; h++) {
                    const int row = bm + warp_m * 64 + mi * 16 + erow + h * 8;
                    float vx = acc[mi][ni][2 * h + 0] + bx;
                    float vy = acc[mi][ni][2 * h + 1] + by;
                    bf162 hh = __floats2bfloat162_rn(vx, vy);
                    float2 hf = __bfloat1622float2(hh);
                    bf162 ll = __floats2bfloat162_rn(vx - hf.x, vy - hf.y);
                    if (sel == 2) {
                        const long off = (long)row * DMODEL + nn;
                        *(bf162*)(Vhi + off) = hh;
                        *(bf162*)(Vlo + off) = ll;
                    } else {
                        char* basep = (char*)((sel == 0) ? Qp : Kp);
                        const long pnl = (long)(row >> 7) * 16 + (nn >> 5);
                        const int r = row & 127, kk = nn & 31;
                        *(bf162*)(basep + (pnl << 14) + off_hi(r, kk)) = hh;
                        *(bf162*)(basep + (pnl << 14) + off_lo(r, kk)) = ll;
                    }
                }
            }
        }
    } else {
        #pragma unroll
        for (int mi = 0; mi < 4; mi++) {
            #pragma unroll
            for (int ni = 0; ni < 8; ni++) {
                const int col = bn + warp_n * 64 + ni * 8 + ecol;
                #pragma unroll
                for (int h = 0; h < 2; h++) {
                    const int row = bm + warp_m * 64 + mi * 16 + erow + h * 8;
                    float2 v;
                    v.x = acc[mi][ni][2 * h + 0] * alpha;
                    v.y = acc[mi][ni][2 * h + 1] * alpha;
                    *(float2*)(Cf + zc + (long)row * N + col) = v;
                }
            }
        }
    }

    if (MODE == MODE_SCORES) {
        // Column softmax partials over this CTA's 256 rows.
        __syncthreads();                              // smem reuse
        float* red_m = (float*)dynsmem;               // [4][128]
        float* red_s = (float*)(dynsmem + 2048);      // [4][128]

        float lm[8][2];
        #pragma unroll
        for (int ni = 0; ni < 8; ni++)
            #pragma unroll
            for (int cc = 0; cc < 2; cc++) {
                float m = -INFINITY;
                #pragma unroll
                for (int mi = 0; mi < 4; mi++)
                    #pragma unroll
                    for (int h = 0; h < 2; h++)
                        m = fmaxf(m, acc[mi][ni][2 * h + cc] * alpha);
                lm[ni][cc] = m;
            }
        #pragma unroll
        for (int off = 4; off < 32; off <<= 1)
            #pragma unroll
            for (int ni = 0; ni < 8; ni++)
                #pragma unroll
                for (int cc = 0; cc < 2; cc++)
                    lm[ni][cc] = fmaxf(lm[ni][cc],
                        __shfl_xor_sync(0xffffffffu, lm[ni][cc], off));
        if (lane < 4) {
            #pragma unroll
            for (int ni = 0; ni < 8; ni++)
                #pragma unroll
                for (int cc = 0; cc < 2; cc++)
                    red_m[warp_m * 128 + warp_n * 64 + ni * 8 + 2 * lane + cc] = lm[ni][cc];
        }
        __syncthreads();

        float cmax[8][2], lsum[8][2];
        #pragma unroll
        for (int ni = 0; ni < 8; ni++)
            #pragma unroll
            for (int cc = 0; cc < 2; cc++) {
                const int cl = warp_n * 64 + ni * 8 + ecol + cc;
                float m = fmaxf(fmaxf(red_m[cl], red_m[128 + cl]),
                                fmaxf(red_m[256 + cl], red_m[384 + cl]));
                cmax[ni][cc] = m;
                float s = 0.f;
                #pragma unroll
                for (int mi = 0; mi < 4; mi++)
                    #pragma unroll
                    for (int h = 0; h < 2; h++)
                        s += __expf(acc[mi][ni][2 * h + cc] * alpha - m);
                lsum[ni][cc] = s;
            }
        #pragma unroll
        for (int off = 4; off < 32; off <<= 1)
            #pragma unroll
            for (int ni = 0; ni < 8; ni++)
                #pragma unroll
                for (int cc = 0; cc < 2; cc++)
                    lsum[ni][cc] += __shfl_xor_sync(0xffffffffu, lsum[ni][cc], off);
        if (lane < 4) {
            #pragma unroll
            for (int ni = 0; ni < 8; ni++)
                #pragma unroll
                for (int cc = 0; cc < 2; cc++)
                    red_s[warp_m * 128 + warp_n * 64 + ni * 8 + 2 * lane + cc] = lsum[ni][cc];
        }
        __syncthreads();

        if (warp_m == 0 && lane < 4) {
            const long pbase = ((long)blockIdx.z * ICH + blockIdx.y) * SEQ + bn;
            #pragma unroll
            for (int ni = 0; ni < 8; ni++)
                #pragma unroll
                for (int cc = 0; cc < 2; cc++) {
                    const int cl = warp_n * 64 + ni * 8 + 2 * lane + cc;
                    pm[pbase + cl] = cmax[ni][cc];
                    ps[pbase + cl] = red_s[cl] + red_s[128 + cl]
                                   + red_s[256 + cl] + red_s[384 + cl];
                }
        }
    }
}

// ---------------------------------------------------------------------------
// x fp32 -> split panels (4 elems per thread, same 16B chunk)
// ---------------------------------------------------------------------------
__global__ void split_x(const float* __restrict__ src, bf16* __restrict__ dst)
{
    const long i = (long)blockIdx.x * blockDim.x + threadIdx.x;
    const long e4 = i * 4;
    const int row = (int)(e4 >> 9);
    const int k = (int)(e4 & 511);
    float4 a = ((const float4*)src)[i];
    bf162 h0 = __floats2bfloat162_rn(a.x, a.y);
    bf162 h1 = __floats2bfloat162_rn(a.z, a.w);
    float2 f0 = __bfloat1622float2(h0);
    float2 f1 = __bfloat1622float2(h1);
    bf162 l0 = __floats2bfloat162_rn(a.x - f0.x, a.y - f0.y);
    bf162 l1 = __floats2bfloat162_rn(a.z - f1.x, a.w - f1.y);
    const long pnl = (long)(row >> 7) * 16 + (k >> 5);
    const int r = row & 127, kk = k & 31;
    char* base = (char*)dst + (pnl << 14);
    union { bf162 v[2]; uint2 u; } uh, ul;
    uh.v[0] = h0; uh.v[1] = h1;
    ul.v[0] = l0; ul.v[1] = l1;
    *(uint2*)(base + off_hi(r, kk)) = uh.u;
    *(uint2*)(base + off_lo(r, kk)) = ul.u;
}

// ---------------------------------------------------------------------------
// W fp32 [K][N] -> Wt split panels [n][k]; grid.z selects W
// ---------------------------------------------------------------------------
__global__ void transpose_split_w(const float* __restrict__ W0,
                                  const float* __restrict__ W1,
                                  const float* __restrict__ W2,
                                  bf16* __restrict__ T)
{
    __shared__ float tile[32][33];
    const int w = blockIdx.z;
    const float* W = (w == 0) ? W0 : (w == 1) ? W1 : W2;
    const int k0 = blockIdx.y * 32, n0 = blockIdx.x * 32;
    const int tx = threadIdx.x, ty = threadIdx.y;
    #pragma unroll
    for (int yy = 0; yy < 32; yy += 8)
        tile[ty + yy][tx] = W[(long)(k0 + ty + yy) * DMODEL + n0 + tx];
    __syncthreads();
    #pragma unroll
    for (int yy = 0; yy < 32; yy += 8) {
        float v = tile[tx][ty + yy];
        bf16 h = __float2bfloat16_rn(v);
        bf16 l = __float2bfloat16_rn(v - __bfloat162float(h));
        const int ng = w * DMODEL + n0 + ty + yy;
        const int k = k0 + tx;
        const long pnl = (long)(ng >> 7) * 16 + (k >> 5);
        char* base = (char*)T + (pnl << 14);
        *(bf16*)(base + off_hi(ng & 127, k & 31)) = h;
        *(bf16*)(base + off_lo(ng & 127, k & 31)) = l;
    }
}

// ---------------------------------------------------------------------------
// Linear split V -> Vt panels [b][e rows][j], KC=64
// ---------------------------------------------------------------------------
__global__ void transpose_v(const bf16* __restrict__ Vhi, const bf16* __restrict__ Vlo,
                            bf16* __restrict__ Vt)
{
    __shared__ bf16 th[32][33], tl[32][33];
    const long b = blockIdx.z;
    const int e0 = blockIdx.x * 32, n0 = blockIdx.y * 32;
    const int tx = threadIdx.x, ty = threadIdx.y;
    #pragma unroll
    for (int yy = 0; yy < 32; yy += 8) {
        const long src = (b * SEQ + n0 + ty + yy) * DMODEL + e0 + tx;
        th[ty + yy][tx] = Vhi[src];
        tl[ty + yy][tx] = Vlo[src];
    }
    __syncthreads();
    char* bbase = (char*)Vt + b * ((long)DMODEL * SEQ * 4);
    #pragma unroll
    for (int yy = 0; yy < 32; yy += 8) {
        const int e = e0 + ty + yy;
        const int j = n0 + tx;
        const long pnl = (long)(e >> 7) * 64 + (j >> 5);
        char* base = bbase + (pnl << 14);
        *(bf16*)(base + off_hi(e & 127, j & 31)) = th[tx][ty + yy];
        *(bf16*)(base + off_lo(e & 127, j & 31)) = tl[tx][ty + yy];
    }
}

// ---------------------------------------------------------------------------
// Softmax combine + normalize; pass3 writes fp32 output AND W panels (KC=64)
// ---------------------------------------------------------------------------
__global__ void sm_pass2(const float* __restrict__ pm, const float* __restrict__ ps,
                         float* __restrict__ gm, float* __restrict__ gi)
{
    const int j = blockIdx.x * blockDim.x + threadIdx.x;
    const long b = blockIdx.y;
    float m = -INFINITY;
    #pragma unroll
    for (int ic = 0; ic < ICH; ic++)
        m = fmaxf(m, pm[(b * ICH + ic) * SEQ + j]);
    float s = 0.0f;
    #pragma unroll
    for (int ic = 0; ic < ICH; ic++)
        s += ps[(b * ICH + ic) * SEQ + j] * __expf(pm[(b * ICH + ic) * SEQ + j] - m);
    gm[b * SEQ + j] = m;
    gi[b * SEQ + j] = 1.0f / s;
}

__global__ void sm_pass3(float* __restrict__ S,
                         const float* __restrict__ gm, const float* __restrict__ gi,
                         bf16* __restrict__ Wp)
{
    const int j4 = (blockIdx.x * blockDim.x + threadIdx.x) * 4;
    const int i = blockIdx.y;
    const long b = blockIdx.z;
    const long off = b * (long)SEQ * SEQ + (long)i * SEQ + j4;
    float4 x = *(const float4*)(S + off);
    float4 m = *(const float4*)(gm + b * SEQ + j4);
    float4 v = *(const float4*)(gi + b * SEQ + j4);
    float4 w;
    w.x = __expf(x.x - m.x) * v.x;
    w.y = __expf(x.y - m.y) * v.y;
    w.z = __expf(x.z - m.z) * v.z;
    w.w = __expf(x.w - m.w) * v.w;
    *(float4*)(S + off) = w;
    bf162 h0 = __floats2bfloat162_rn(w.x, w.y);
    bf162 h1 = __floats2bfloat162_rn(w.z, w.w);
    float2 f0 = __bfloat1622float2(h0);
    float2 f1 = __bfloat1622float2(h1);
    bf162 l0 = __floats2bfloat162_rn(w.x - f0.x, w.y - f0.y);
    bf162 l1 = __floats2bfloat162_rn(w.z - f1.x, w.w - f1.y);
    char* bbase = (char*)Wp + b * ((long)SEQ * SEQ * 4);
    const long pnl = (long)(i >> 7) * 64 + (j4 >> 5);
    char* base = bbase + (pnl << 14);
    const int r = i & 127, kk = j4 & 31;
    union { bf162 v[2]; uint2 u; } uh, ul;
    uh.v[0] = h0; uh.v[1] = h1;
    ul.v[0] = l0; ul.v[1] = l1;
    *(uint2*)(base + off_hi(r, kk)) = uh.u;
    *(uint2*)(base + off_lo(r, kk)) = ul.u;
}

// ---------------------------------------------------------------------------
// kernel_launch
// ---------------------------------------------------------------------------
extern "C" void kernel_launch(void* const* d_in, const int* in_sizes, int n_in,
                              void* d_out, int out_size)
{
    const float* x  = (const float*)d_in[0];
    const float* Wq = (const float*)d_in[1];
    const float* bq = (const float*)d_in[2];
    const float* Wk = (const float*)d_in[3];
    const float* bk = (const float*)d_in[4];
    const float* Wv = (const float*)d_in[5];
    const float* bv = (const float*)d_in[6];

    float* out     = (float*)d_out;
    float* weights = out + (long)BATCH * SEQ * DMODEL;

    bf16 *xp, *Wtp, *Qp, *Kp, *Vhi, *Vlo, *Vtp, *Wp;
    float *pm, *ps, *gm, *gi;
    cudaGetSymbolAddress((void**)&xp, g_x);
    cudaGetSymbolAddress((void**)&Wtp, g_Wt);
    cudaGetSymbolAddress((void**)&Qp, g_Q);
    cudaGetSymbolAddress((void**)&Kp, g_K);
    cudaGetSymbolAddress((void**)&Vhi, g_Vhi);
    cudaGetSymbolAddress((void**)&Vlo, g_Vlo);
    cudaGetSymbolAddress((void**)&Vtp, g_Vt);
    cudaGetSymbolAddress((void**)&Wp, g_W);
    cudaGetSymbolAddress((void**)&pm, g_pm);
    cudaGetSymbolAddress((void**)&ps, g_ps);
    cudaGetSymbolAddress((void**)&gm, g_gm);
    cudaGetSymbolAddress((void**)&gi, g_gi);

    static bool attr_set = false;
    if (!attr_set) {
        cudaFuncSetAttribute(gemm_ps<MODE_PROJ>,
                             cudaFuncAttributeMaxDynamicSharedMemorySize, DYN_SMEM);
        cudaFuncSetAttribute(gemm_ps<MODE_SCORES>,
                             cudaFuncAttributeMaxDynamicSharedMemorySize, DYN_SMEM);
        cudaFuncSetAttribute(gemm_ps<MODE_AV>,
                             cudaFuncAttributeMaxDynamicSharedMemorySize, DYN_SMEM);
        attr_set = true;
    }

    const dim3 blk(256);

    // 0) inputs -> panel layout
    split_x<<<(BATCH * SEQ * DMODEL / 4) / 256, blk>>>(x, xp);
    {
        dim3 g(16, 16, 3), b(32, 8);
        transpose_split_w<<<g, b>>>(Wq, Wk, Wv, Wtp);
    }

    // 1) fused QKV projection: A = x panels, B = Wt panels (KC = 16)
    {
        dim3 grid(3 * DMODEL / BN, (BATCH * SEQ) / BM, 1);
        gemm_ps<MODE_PROJ><<<grid, blk, DYN_SMEM>>>(
            (const char*)xp, (const char*)Wtp, 1.0f, 3 * DMODEL, DMODEL / 32,
            0, 0, 0, nullptr, nullptr, nullptr, bq, bk, bv, Qp, Kp, Vhi, Vlo);
    }

    // 1b) V -> Vt panels
    {
        dim3 g(DMODEL / 32, SEQ / 32, BATCH), b(32, 8);
        transpose_v<<<g, b>>>(Vhi, Vlo, Vtp);
    }

    // 2) scores = scale * Q @ K^T -> weights fp32 + softmax partials (KC = 16)
    {
        const float scale = 1.0f / sqrtf((float)DMODEL);
        dim3 grid(SEQ / BN, SEQ / BM, BATCH);
        gemm_ps<MODE_SCORES><<<grid, blk, DYN_SMEM>>>(
            (const char*)Qp, (const char*)Kp, scale, SEQ, DMODEL / 32,
            (long)SEQ * DMODEL * 4, (long)SEQ * DMODEL * 4, (long)SEQ * SEQ,
            weights, pm, ps, nullptr, nullptr, nullptr,
            nullptr, nullptr, nullptr, nullptr);
    }

    // 3) softmax combine + normalize (pass3 emits W panels)
    {
        dim3 g2(SEQ / 256, BATCH);
        sm_pass2<<<g2, blk>>>(pm, ps, gm, gi);
        dim3 g3(SEQ / (256 * 4), SEQ, BATCH);
        sm_pass3<<<g3, blk>>>(weights, gm, gi, Wp);
    }

    // 4) out = weights @ V: A = W panels, B = Vt panels (KC = 64)
    {
        dim3 grid(DMODEL / BN, SEQ / BM, BATCH);
        gemm_ps<MODE_AV><<<grid, blk, DYN_SMEM>>>(
            (const char*)Wp, (const char*)Vtp, 1.0f, DMODEL, SEQ / 32,
            (long)SEQ * SEQ * 4, (long)DMODEL * SEQ * 4, (long)SEQ * DMODEL,
            out, nullptr, nullptr, nullptr, nullptr, nullptr,
            nullptr, nullptr, nullptr, nullptr);
    }
}

// round 13
// speedup vs baseline: 1.1480x; 1.1480x over previous
#include <cuda_runtime.h>
#include <cuda_bf16.h>
#include <math.h>
#include <stdint.h>

// Problem constants
#define BATCH 8
#define SEQ   2048
#define DMODEL 512

#define BM 128
#define BN 128
// tile: 128 rows x 128B (hi bytes [0,64), lo [64,128)), XOR-swizzled, = 16KB
#define TILE_B  16384
#define STAGE_B (2 * TILE_B)
#define NSTAGE  3
#define DYN_SMEM (NSTAGE * STAGE_B)   // 96 KB

#define ICH 16
#define MODE_PROJ   0
#define MODE_SCORES 1
#define MODE_AV     2

typedef __nv_bfloat16 bf16;
typedef __nv_bfloat162 bf162;

// ---------------------------------------------------------------------------
// Device scratch: panel (tile-major, pre-swizzled) arrays hold hi+lo combined.
// ---------------------------------------------------------------------------
__device__ bf16 g_x[(long)BATCH * SEQ * DMODEL * 2];        // panels, KC=16
__device__ bf16 g_Wt[3L * DMODEL * DMODEL * 2];             // panels, KC=16
__device__ bf16 g_Q[(long)BATCH * SEQ * DMODEL * 2];        // panels, KC=16
__device__ bf16 g_K[(long)BATCH * SEQ * DMODEL * 2];        // panels, KC=16
__device__ bf16 g_Vhi[(long)BATCH * SEQ * DMODEL];          // linear
__device__ bf16 g_Vlo[(long)BATCH * SEQ * DMODEL];          // linear
__device__ bf16 g_Vt[(long)BATCH * DMODEL * SEQ * 2];       // panels, KC=64
__device__ bf16 g_W[(long)BATCH * SEQ * SEQ * 2];           // panels, KC=64
__device__ float g_pm[BATCH * ICH * SEQ], g_ps[BATCH * ICH * SEQ];
__device__ float g_gm[BATCH * SEQ], g_gi[BATCH * SEQ];

// Panel element addressing (within a 16KB tile)
__device__ __forceinline__ uint32_t off_hi(int r, int kk) {
    return (uint32_t)((r << 7) + ((((kk >> 3) << 4) ^ ((r & 7) << 4)) | ((kk & 7) << 1)));
}
__device__ __forceinline__ uint32_t off_lo(int r, int kk) {
    return (uint32_t)((r << 7) + (((((kk >> 3) + 4) << 4) ^ ((r & 7) << 4)) | ((kk & 7) << 1)));
}

// ---------------------------------------------------------------------------
// PTX helpers
// ---------------------------------------------------------------------------
__device__ __forceinline__ uint32_t smem_u32(const void* p) {
    uint32_t a;
    asm("{ .reg .u64 t; cvta.to.shared.u64 t, %1; cvt.u32.u64 %0, t; }"
        : "=r"(a) : "l"(p));
    return a;
}
__device__ __forceinline__ void ldm_x4(uint32_t* r, uint32_t addr) {
    asm volatile("ldmatrix.sync.aligned.m8n8.x4.shared.b16 {%0,%1,%2,%3}, [%4];"
        : "=r"(r[0]), "=r"(r[1]), "=r"(r[2]), "=r"(r[3]) : "r"(addr));
}
__device__ __forceinline__ void mma16816(float* c, const uint32_t* a, const uint32_t* b) {
    asm volatile(
        "mma.sync.aligned.m16n8k16.row.col.f32.bf16.bf16.f32 "
        "{%0,%1,%2,%3}, {%4,%5,%6,%7}, {%8,%9}, {%0,%1,%2,%3};"
        : "+f"(c[0]), "+f"(c[1]), "+f"(c[2]), "+f"(c[3])
        : "r"(a[0]), "r"(a[1]), "r"(a[2]), "r"(a[3]), "r"(b[0]), "r"(b[1]));
}

#define MBARRIER_INIT(addr, cnt) \
    asm volatile("mbarrier.init.shared.b64 [%0], %1;" \
                 :: "r"((uint32_t)(addr)), "r"((uint32_t)(cnt)) : "memory")
#define MBARRIER_EXPECT_TX(addr, bytes) \
    asm volatile("mbarrier.arrive.expect_tx.shared.b64 _, [%0], %1;" \
                 :: "r"((uint32_t)(addr)), "r"((uint32_t)(bytes)) : "memory")
#define MBARRIER_ARRIVE(addr) \
    asm volatile("mbarrier.arrive.shared.b64 _, [%0];" \
                 :: "r"((uint32_t)(addr)) : "memory")
#define CP_BULK(dst, src, bytes, bar) \
    asm volatile("cp.async.bulk.shared::cta.global.mbarrier::complete_tx::bytes " \
                 "[%0], [%1], %2, [%3];" \
                 :: "r"((uint32_t)(dst)), "l"(src), "r"((uint32_t)(bytes)), \
                    "r"((uint32_t)(bar)) : "memory")
#define FENCE_PROXY_ASYNC() \
    asm volatile("fence.proxy.async.shared::cta;" ::: "memory")

#define MBARRIER_WAIT_PARITY(mbar_smem_addr, phase_parity) do { \
    uint32_t _mbar = (uint32_t)(mbar_smem_addr); \
    uint32_t _parity = (uint32_t)(phase_parity); \
    uint32_t _done; \
    asm volatile( \
        "{\n\t.reg .pred p;\n\t" \
        "mbarrier.try_wait.parity.acquire.cta.shared::cta.b64 p, [%1], %2;\n\t" \
        "selp.b32 %0, 1, 0, p;\n\t}" \
        : "=r"(_done) : "r"(_mbar), "r"(_parity) : "memory"); \
    if (!_done) { \
        asm volatile( \
            "{\n\t.reg .pred P1;\n\t" \
            "WAIT_LOOP_%=:\n\t" \
            "mbarrier.try_wait.parity.acquire.cta.shared::cta.b64 P1, [%0], %1, 0x989680;\n\t" \
            "@P1 bra.uni WAIT_DONE_%=;\n\t" \
            "bra.uni WAIT_LOOP_%=;\n\t" \
            "WAIT_DONE_%=:\n\t}" \
            :: "r"(_mbar), "r"(_parity) : "memory"); \
    } \
} while(0)

// ===========================================================================
// GEMM on panel-layout split bf16, 3-term split (hh+hl+lh).
// Tiles fetched with cp.async.bulk (16KB each) into a 3-stage smem ring with
// full/empty mbarriers (no per-chunk __syncthreads).
// CTA tile 128x128, 256 threads (2 warp_m x 4 warp_n, 64x32 warp tiles).
// ===========================================================================
template<int MODE>
__global__ __launch_bounds__(256, 2)
void gemm_ps(const char* __restrict__ Ab, const char* __restrict__ Bb,
             float alpha, int N, int KC, long sA, long sB, long sC,
             float* __restrict__ Cf,
             float* __restrict__ pm, float* __restrict__ ps,
             const float* __restrict__ bq, const float* __restrict__ bk,
             const float* __restrict__ bv,
             bf16* __restrict__ Qp, bf16* __restrict__ Kp,
             bf16* __restrict__ Vhi, bf16* __restrict__ Vlo)
{
    const char* A = Ab + (long)blockIdx.z * sA;
    const char* B = Bb + (long)blockIdx.z * sB;
    const long zc = (long)blockIdx.z * sC;
    const int bm = blockIdx.y * BM;
    const int bn = blockIdx.x * BN;
    const int tid = threadIdx.x;
    const int wid = tid >> 5, lane = tid & 31;
    const int warp_m = wid & 1;
    const int warp_n = wid >> 1;

    extern __shared__ __align__(16) char dynsmem[];
    const uint32_t sbase = smem_u32(dynsmem);
    __shared__ __align__(8) unsigned long long s_bar[NSTAGE];
    __shared__ __align__(8) unsigned long long s_emp[NSTAGE];
    const uint32_t bar0 = smem_u32(s_bar);
    const uint32_t emp0 = smem_u32(s_emp);

    if (tid == 0) {
        #pragma unroll
        for (int s = 0; s < NSTAGE; s++) {
            MBARRIER_INIT(bar0 + s * 8, 1);
            MBARRIER_INIT(emp0 + s * 8, 256);
        }
        FENCE_PROXY_ASYNC();
    }
    __syncthreads();

    float acc[4][4][4] = {};

    const int a_row = warp_m * 64 + (lane & 15);
    const uint32_t a_k = (uint32_t)(((lane >> 4) * 8) * 2);
    const int b_row = warp_n * 32 + (lane & 7) + ((lane >> 4) * 8);
    const uint32_t b_k = (uint32_t)((((lane >> 3) & 1) * 8) * 2);
    const uint32_t swz = (uint32_t)((lane & 7) << 4);

    const int nch = KC;
    const long pA = (long)blockIdx.y * KC;   // A panel row-block
    const long pB = (long)blockIdx.x * KC;

    // Prologue: issue chunks 0 and 1 (chunk 2 issued at c=0 in the loop)
    if (tid == 0) {
        #pragma unroll
        for (int c = 0; c < 2; c++) {
            const uint32_t bar = bar0 + c * 8;
            MBARRIER_EXPECT_TX(bar, 2 * TILE_B);
            CP_BULK(sbase + c * STAGE_B,          A + ((pA + c) << 14), TILE_B, bar);
            CP_BULK(sbase + c * STAGE_B + TILE_B, B + ((pB + c) << 14), TILE_B, bar);
        }
    }

    for (int c = 0; c < nch; c++) {
        // Producer: issue chunk c+2 into stage (c+2)%3 once its previous
        // consumers have all arrived on the stage's empty barrier.
        if (tid == 0 && c + 2 < nch) {
            const int s = (c + 2) % NSTAGE;
            if (c + 2 >= NSTAGE)
                MBARRIER_WAIT_PARITY(emp0 + s * 8, (((c + 2) / NSTAGE) - 1) & 1);
            const uint32_t bar = bar0 + s * 8;
            MBARRIER_EXPECT_TX(bar, 2 * TILE_B);
            CP_BULK(sbase + s * STAGE_B,          A + ((pA + c + 2) << 14), TILE_B, bar);
            CP_BULK(sbase + s * STAGE_B + TILE_B, B + ((pB + c + 2) << 14), TILE_B, bar);
        }

        const int st = c % NSTAGE;
        MBARRIER_WAIT_PARITY(bar0 + st * 8, (c / NSTAGE) & 1);

        const uint32_t uA = sbase + st * STAGE_B;
        const uint32_t uB = uA + TILE_B;

        #pragma unroll
        for (int ks = 0; ks < 2; ks++) {
            const uint32_t akh = ((a_k + ks * 32) ^ swz);
            const uint32_t akl = ((a_k + ks * 32 + 64) ^ swz);
            const uint32_t bkh = ((b_k + ks * 32) ^ swz);
            const uint32_t bkl = ((b_k + ks * 32 + 64) ^ swz);
            uint32_t afh[4][4], afl[4][4], bfh[2][4], bfl[2][4];
            // Load afh, bfh, bfl up front -> LDSM latency hides under hh MMAs
            #pragma unroll
            for (int mi = 0; mi < 4; mi++)
                ldm_x4(afh[mi], uA + (uint32_t)((a_row + mi * 16) * 128) + akh);
            #pragma unroll
            for (int nb2 = 0; nb2 < 2; nb2++)
                ldm_x4(bfh[nb2], uB + (uint32_t)((b_row + nb2 * 16) * 128) + bkh);
            #pragma unroll
            for (int nb2 = 0; nb2 < 2; nb2++)
                ldm_x4(bfl[nb2], uB + (uint32_t)((b_row + nb2 * 16) * 128) + bkl);
            #pragma unroll
            for (int mi = 0; mi < 4; mi++)
                #pragma unroll
                for (int ni = 0; ni < 4; ni++)
                    mma16816(acc[mi][ni], afh[mi], &bfh[ni >> 1][(ni & 1) * 2]);
            #pragma unroll
            for (int mi = 0; mi < 4; mi++)
                ldm_x4(afl[mi], uA + (uint32_t)((a_row + mi * 16) * 128) + akl);
            #pragma unroll
            for (int mi = 0; mi < 4; mi++)
                #pragma unroll
                for (int ni = 0; ni < 4; ni++)
                    mma16816(acc[mi][ni], afh[mi], &bfl[ni >> 1][(ni & 1) * 2]);
            #pragma unroll
            for (int mi = 0; mi < 4; mi++)
                #pragma unroll
                for (int ni = 0; ni < 4; ni++)
                    mma16816(acc[mi][ni], afl[mi], &bfh[ni >> 1][(ni & 1) * 2]);
        }
        // All smem reads for this chunk done (LDSM is synchronous) -> release
        MBARRIER_ARRIVE(emp0 + st * 8);
    }

    // ---------------- Epilogue ----------------
    const int erow = lane >> 2;
    const int ecol = 2 * (lane & 3);

    if (MODE == MODE_PROJ) {
        #pragma unroll
        for (int mi = 0; mi < 4; mi++) {
            #pragma unroll
            for (int ni = 0; ni < 4; ni++) {
                const int col = bn + warp_n * 32 + ni * 8 + ecol;
                const int sel = col >> 9;
                const int nn = col & 511;
                const float* bp = (sel == 0) ? bq : (sel == 1) ? bk : bv;
                const float bx = bp[nn], by = bp[nn + 1];
                #pragma unroll
                for (int h = 0; h < 2; h++) {
                    const int row = bm + warp_m * 64 + mi * 16 + erow + h * 8;
                    float vx = acc[mi][ni][2 * h + 0] + bx;
                    float vy = acc[mi][ni][2 * h + 1] + by;
                    bf162 hh = __floats2bfloat162_rn(vx, vy);
                    float2 hf = __bfloat1622float2(hh);
                    bf162 ll = __floats2bfloat162_rn(vx - hf.x, vy - hf.y);
                    if (sel == 2) {
                        const long off = (long)row * DMODEL + nn;
                        *(bf162*)(Vhi + off) = hh;
                        *(bf162*)(Vlo + off) = ll;
                    } else {
                        char* basep = (char*)((sel == 0) ? Qp : Kp);
                        const long pnl = (long)(row >> 7) * 16 + (nn >> 5);
                        const int r = row & 127, kk = nn & 31;
                        *(bf162*)(basep + (pnl << 14) + off_hi(r, kk)) = hh;
                        *(bf162*)(basep + (pnl << 14) + off_lo(r, kk)) = ll;
                    }
                }
            }
        }
    } else {
        #pragma unroll
        for (int mi = 0; mi < 4; mi++) {
            #pragma unroll
            for (int ni = 0; ni < 4; ni++) {
                const int col = bn + warp_n * 32 + ni * 8 + ecol;
                #pragma unroll
                for (int h = 0; h < 2; h++) {
                    const int row = bm + warp_m * 64 + mi * 16 + erow + h * 8;
                    float2 v;
                    v.x = acc[mi][ni][2 * h + 0] * alpha;
                    v.y = acc[mi][ni][2 * h + 1] * alpha;
                    *(float2*)(Cf + zc + (long)row * N + col) = v;
                }
            }
        }
    }

    if (MODE == MODE_SCORES) {
        __syncthreads();                             // smem reuse after loop
        float* red_m = (float*)dynsmem;              // [2][128]
        float* red_s = (float*)(dynsmem + 1024);     // [2][128]

        float lm[4][2];
        #pragma unroll
        for (int ni = 0; ni < 4; ni++)
            #pragma unroll
            for (int cc = 0; cc < 2; cc++) {
                float m = -INFINITY;
                #pragma unroll
                for (int mi = 0; mi < 4; mi++)
                    #pragma unroll
                    for (int h = 0; h < 2; h++)
                        m = fmaxf(m, acc[mi][ni][2 * h + cc] * alpha);
                lm[ni][cc] = m;
            }
        #pragma unroll
        for (int off = 4; off < 32; off <<= 1)
            #pragma unroll
            for (int ni = 0; ni < 4; ni++)
                #pragma unroll
                for (int cc = 0; cc < 2; cc++)
                    lm[ni][cc] = fmaxf(lm[ni][cc],
                        __shfl_xor_sync(0xffffffffu, lm[ni][cc], off));
        if (lane < 4) {
            #pragma unroll
            for (int ni = 0; ni < 4; ni++)
                #pragma unroll
                for (int cc = 0; cc < 2; cc++)
                    red_m[warp_m * 128 + warp_n * 32 + ni * 8 + 2 * lane + cc] = lm[ni][cc];
        }
        __syncthreads();

        float cmax[4][2], lsum[4][2];
        #pragma unroll
        for (int ni = 0; ni < 4; ni++)
            #pragma unroll
            for (int cc = 0; cc < 2; cc++) {
                const int cl = warp_n * 32 + ni * 8 + ecol + cc;
                cmax[ni][cc] = fmaxf(red_m[cl], red_m[128 + cl]);
                float s = 0.f;
                #pragma unroll
                for (int mi = 0; mi < 4; mi++)
                    #pragma unroll
                    for (int h = 0; h < 2; h++)
                        s += __expf(acc[mi][ni][2 * h + cc] * alpha - cmax[ni][cc]);
                lsum[ni][cc] = s;
            }
        #pragma unroll
        for (int off = 4; off < 32; off <<= 1)
            #pragma unroll
            for (int ni = 0; ni < 4; ni++)
                #pragma unroll
                for (int cc = 0; cc < 2; cc++)
                    lsum[ni][cc] += __shfl_xor_sync(0xffffffffu, lsum[ni][cc], off);
        if (lane < 4) {
            #pragma unroll
            for (int ni = 0; ni < 4; ni++)
                #pragma unroll
                for (int cc = 0; cc < 2; cc++)
                    red_s[warp_m * 128 + warp_n * 32 + ni * 8 + 2 * lane + cc] = lsum[ni][cc];
        }
        __syncthreads();

        if (warp_m == 0 && lane < 4) {
            const long pbase = ((long)blockIdx.z * ICH + blockIdx.y) * SEQ + bn;
            #pragma unroll
            for (int ni = 0; ni < 4; ni++)
                #pragma unroll
                for (int cc = 0; cc < 2; cc++) {
                    const int cl = warp_n * 32 + ni * 8 + 2 * lane + cc;
                    pm[pbase + cl] = cmax[ni][cc];
                    ps[pbase + cl] = red_s[cl] + red_s[128 + cl];
                }
        }
    }
}

// ---------------------------------------------------------------------------
// x fp32 -> split panels (4 elems per thread, same 16B chunk)
// ---------------------------------------------------------------------------
__global__ void split_x(const float* __restrict__ src, bf16* __restrict__ dst)
{
    const long i = (long)blockIdx.x * blockDim.x + threadIdx.x;
    const long e4 = i * 4;
    const int row = (int)(e4 >> 9);
    const int k = (int)(e4 & 511);
    float4 a = ((const float4*)src)[i];
    bf162 h0 = __floats2bfloat162_rn(a.x, a.y);
    bf162 h1 = __floats2bfloat162_rn(a.z, a.w);
    float2 f0 = __bfloat1622float2(h0);
    float2 f1 = __bfloat1622float2(h1);
    bf162 l0 = __floats2bfloat162_rn(a.x - f0.x, a.y - f0.y);
    bf162 l1 = __floats2bfloat162_rn(a.z - f1.x, a.w - f1.y);
    const long pnl = (long)(row >> 7) * 16 + (k >> 5);
    const int r = row & 127, kk = k & 31;
    char* base = (char*)dst + (pnl << 14);
    union { bf162 v[2]; uint2 u; } uh, ul;
    uh.v[0] = h0; uh.v[1] = h1;
    ul.v[0] = l0; ul.v[1] = l1;
    *(uint2*)(base + off_hi(r, kk)) = uh.u;
    *(uint2*)(base + off_lo(r, kk)) = ul.u;
}

// ---------------------------------------------------------------------------
// W fp32 [K][N] -> Wt split panels [n][k]; grid.z selects W
// ---------------------------------------------------------------------------
__global__ void transpose_split_w(const float* __restrict__ W0,
                                  const float* __restrict__ W1,
                                  const float* __restrict__ W2,
                                  bf16* __restrict__ T)
{
    __shared__ float tile[32][33];
    const int w = blockIdx.z;
    const float* W = (w == 0) ? W0 : (w == 1) ? W1 : W2;
    const int k0 = blockIdx.y * 32, n0 = blockIdx.x * 32;
    const int tx = threadIdx.x, ty = threadIdx.y;
    #pragma unroll
    for (int yy = 0; yy < 32; yy += 8)
        tile[ty + yy][tx] = W[(long)(k0 + ty + yy) * DMODEL + n0 + tx];
    __syncthreads();
    #pragma unroll
    for (int yy = 0; yy < 32; yy += 8) {
        float v = tile[tx][ty + yy];
        bf16 h = __float2bfloat16_rn(v);
        bf16 l = __float2bfloat16_rn(v - __bfloat162float(h));
        const int ng = w * DMODEL + n0 + ty + yy;
        const int k = k0 + tx;
        const long pnl = (long)(ng >> 7) * 16 + (k >> 5);
        char* base = (char*)T + (pnl << 14);
        *(bf16*)(base + off_hi(ng & 127, k & 31)) = h;
        *(bf16*)(base + off_lo(ng & 127, k & 31)) = l;
    }
}

// ---------------------------------------------------------------------------
// Linear split V -> Vt panels [b][e rows][j], KC=64
// ---------------------------------------------------------------------------
__global__ void transpose_v(const bf16* __restrict__ Vhi, const bf16* __restrict__ Vlo,
                            bf16* __restrict__ Vt)
{
    __shared__ bf16 th[32][33], tl[32][33];
    const long b = blockIdx.z;
    const int e0 = blockIdx.x * 32, n0 = blockIdx.y * 32;
    const int tx = threadIdx.x, ty = threadIdx.y;
    #pragma unroll
    for (int yy = 0; yy < 32; yy += 8) {
        const long src = (b * SEQ + n0 + ty + yy) * DMODEL + e0 + tx;
        th[ty + yy][tx] = Vhi[src];
        tl[ty + yy][tx] = Vlo[src];
    }
    __syncthreads();
    char* bbase = (char*)Vt + b * ((long)DMODEL * SEQ * 4);
    #pragma unroll
    for (int yy = 0; yy < 32; yy += 8) {
        const int e = e0 + ty + yy;
        const int j = n0 + tx;
        const long pnl = (long)(e >> 7) * 64 + (j >> 5);
        char* base = bbase + (pnl << 14);
        *(bf16*)(base + off_hi(e & 127, j & 31)) = th[tx][ty + yy];
        *(bf16*)(base + off_lo(e & 127, j & 31)) = tl[tx][ty + yy];
    }
}

// ---------------------------------------------------------------------------
// Softmax combine + normalize; pass3 writes fp32 output AND W panels (KC=64)
// ---------------------------------------------------------------------------
__global__ void sm_pass2(const float* __restrict__ pm, const float* __restrict__ ps,
                         float* __restrict__ gm, float* __restrict__ gi)
{
    const int j = blockIdx.x * blockDim.x + threadIdx.x;
    const long b = blockIdx.y;
    float m = -INFINITY;
    #pragma unroll
    for (int ic = 0; ic < ICH; ic++)
        m = fmaxf(m, pm[(b * ICH + ic) * SEQ + j]);
    float s = 0.0f;
    #pragma unroll
    for (int ic = 0; ic < ICH; ic++)
        s += ps[(b * ICH + ic) * SEQ + j] * __expf(pm[(b * ICH + ic) * SEQ + j] - m);
    gm[b * SEQ + j] = m;
    gi[b * SEQ + j] = 1.0f / s;
}

__global__ void sm_pass3(float* __restrict__ S,
                         const float* __restrict__ gm, const float* __restrict__ gi,
                         bf16* __restrict__ Wp)
{
    const int j4 = (blockIdx.x * blockDim.x + threadIdx.x) * 4;
    const int i = blockIdx.y;
    const long b = blockIdx.z;
    const long off = b * (long)SEQ * SEQ + (long)i * SEQ + j4;
    float4 x = *(const float4*)(S + off);
    float4 m = *(const float4*)(gm + b * SEQ + j4);
    float4 v = *(const float4*)(gi + b * SEQ + j4);
    float4 w;
    w.x = __expf(x.x - m.x) * v.x;
    w.y = __expf(x.y - m.y) * v.y;
    w.z = __expf(x.z - m.z) * v.z;
    w.w = __expf(x.w - m.w) * v.w;
    *(float4*)(S + off) = w;
    bf162 h0 = __floats2bfloat162_rn(w.x, w.y);
    bf162 h1 = __floats2bfloat162_rn(w.z, w.w);
    float2 f0 = __bfloat1622float2(h0);
    float2 f1 = __bfloat1622float2(h1);
    bf162 l0 = __floats2bfloat162_rn(w.x - f0.x, w.y - f0.y);
    bf162 l1 = __floats2bfloat162_rn(w.z - f1.x, w.w - f1.y);
    char* bbase = (char*)Wp + b * ((long)SEQ * SEQ * 4);
    const long pnl = (long)(i >> 7) * 64 + (j4 >> 5);
    char* base = bbase + (pnl << 14);
    const int r = i & 127, kk = j4 & 31;
    union { bf162 v[2]; uint2 u; } uh, ul;
    uh.v[0] = h0; uh.v[1] = h1;
    ul.v[0] = l0; ul.v[1] = l1;
    *(uint2*)(base + off_hi(r, kk)) = uh.u;
    *(uint2*)(base + off_lo(r, kk)) = ul.u;
}

// ---------------------------------------------------------------------------
// kernel_launch
// ---------------------------------------------------------------------------
extern "C" void kernel_launch(void* const* d_in, const int* in_sizes, int n_in,
                              void* d_out, int out_size)
{
    const float* x  = (const float*)d_in[0];
    const float* Wq = (const float*)d_in[1];
    const float* bq = (const float*)d_in[2];
    const float* Wk = (const float*)d_in[3];
    const float* bk = (const float*)d_in[4];
    const float* Wv = (const float*)d_in[5];
    const float* bv = (const float*)d_in[6];

    float* out     = (float*)d_out;
    float* weights = out + (long)BATCH * SEQ * DMODEL;

    bf16 *xp, *Wtp, *Qp, *Kp, *Vhi, *Vlo, *Vtp, *Wp;
    float *pm, *ps, *gm, *gi;
    cudaGetSymbolAddress((void**)&xp, g_x);
    cudaGetSymbolAddress((void**)&Wtp, g_Wt);
    cudaGetSymbolAddress((void**)&Qp, g_Q);
    cudaGetSymbolAddress((void**)&Kp, g_K);
    cudaGetSymbolAddress((void**)&Vhi, g_Vhi);
    cudaGetSymbolAddress((void**)&Vlo, g_Vlo);
    cudaGetSymbolAddress((void**)&Vtp, g_Vt);
    cudaGetSymbolAddress((void**)&Wp, g_W);
    cudaGetSymbolAddress((void**)&pm, g_pm);
    cudaGetSymbolAddress((void**)&ps, g_ps);
    cudaGetSymbolAddress((void**)&gm, g_gm);
    cudaGetSymbolAddress((void**)&gi, g_gi);

    static bool attr_set = false;
    if (!attr_set) {
        cudaFuncSetAttribute(gemm_ps<MODE_PROJ>,
                             cudaFuncAttributeMaxDynamicSharedMemorySize, DYN_SMEM);
        cudaFuncSetAttribute(gemm_ps<MODE_SCORES>,
                             cudaFuncAttributeMaxDynamicSharedMemorySize, DYN_SMEM);
        cudaFuncSetAttribute(gemm_ps<MODE_AV>,
                             cudaFuncAttributeMaxDynamicSharedMemorySize, DYN_SMEM);
        attr_set = true;
    }

    const dim3 blk(256);

    // 0) inputs -> panel layout
    split_x<<<(BATCH * SEQ * DMODEL / 4) / 256, blk>>>(x, xp);
    {
        dim3 g(16, 16, 3), b(32, 8);
        transpose_split_w<<<g, b>>>(Wq, Wk, Wv, Wtp);
    }

    // 1) fused QKV projection: A = x panels, B = Wt panels (KC = 16)
    {
        dim3 grid(3 * DMODEL / BN, (BATCH * SEQ) / BM, 1);
        gemm_ps<MODE_PROJ><<<grid, blk, DYN_SMEM>>>(
            (const char*)xp, (const char*)Wtp, 1.0f, 3 * DMODEL, DMODEL / 32,
            0, 0, 0, nullptr, nullptr, nullptr, bq, bk, bv, Qp, Kp, Vhi, Vlo);
    }

    // 1b) V -> Vt panels
    {
        dim3 g(DMODEL / 32, SEQ / 32, BATCH), b(32, 8);
        transpose_v<<<g, b>>>(Vhi, Vlo, Vtp);
    }

    // 2) scores = scale * Q @ K^T -> weights fp32 + softmax partials (KC = 16)
    {
        const float scale = 1.0f / sqrtf((float)DMODEL);
        dim3 grid(SEQ / BN, SEQ / BM, BATCH);
        gemm_ps<MODE_SCORES><<<grid, blk, DYN_SMEM>>>(
            (const char*)Qp, (const char*)Kp, scale, SEQ, DMODEL / 32,
            (long)SEQ * DMODEL * 4, (long)SEQ * DMODEL * 4, (long)SEQ * SEQ,
            weights, pm, ps, nullptr, nullptr, nullptr,
            nullptr, nullptr, nullptr, nullptr);
    }

    // 3) softmax combine + normalize (pass3 emits W panels)
    {
        dim3 g2(SEQ / 256, BATCH);
        sm_pass2<<<g2, blk>>>(pm, ps, gm, gi);
        dim3 g3(SEQ / (256 * 4), SEQ, BATCH);
        sm_pass3<<<g3, blk>>>(weights, gm, gi, Wp);
    }

    // 4) out = weights @ V: A = W panels, B = Vt panels (KC = 64)
    {
        dim3 grid(DMODEL / BN, SEQ / BM, BATCH);
        gemm_ps<MODE_AV><<<grid, blk, DYN_SMEM>>>(
            (const char*)Wp, (const char*)Vtp, 1.0f, DMODEL, SEQ / 32,
            (long)SEQ * SEQ * 4, (long)DMODEL * SEQ * 4, (long)SEQ * DMODEL,
            out, nullptr, nullptr, nullptr, nullptr, nullptr,
            nullptr, nullptr, nullptr, nullptr);
    }
}

// round 14
// speedup vs baseline: 1.1521x; 1.0035x over previous
#include <cuda_runtime.h>
#include <cuda_bf16.h>
#include <math.h>
#include <stdint.h>

// Problem constants
#define BATCH 8
#define SEQ   2048
#define DMODEL 512

#define BM 128
#define BN 128
// tile: 128 rows x 128B (hi bytes [0,64), lo [64,128)), XOR-swizzled, = 16KB
#define TILE_B  16384
#define STAGE_B (2 * TILE_B)
#define NSTAGE  3
#define DYN_SMEM (NSTAGE * STAGE_B)   // 96 KB

#define ICH 16
#define MODE_PROJ   0
#define MODE_SCORES 1
#define MODE_AV     2

typedef __nv_bfloat16 bf16;
typedef __nv_bfloat162 bf162;

// ---------------------------------------------------------------------------
// Device scratch: panel (tile-major, pre-swizzled) arrays hold hi+lo combined.
// ---------------------------------------------------------------------------
__device__ bf16 g_x[(long)BATCH * SEQ * DMODEL * 2];        // panels, KC=16
__device__ bf16 g_Wt[3L * DMODEL * DMODEL * 2];             // panels, KC=16
__device__ bf16 g_Q[(long)BATCH * SEQ * DMODEL * 2];        // panels, KC=16
__device__ bf16 g_K[(long)BATCH * SEQ * DMODEL * 2];        // panels, KC=16
__device__ bf16 g_Vhi[(long)BATCH * SEQ * DMODEL];          // linear
__device__ bf16 g_Vlo[(long)BATCH * SEQ * DMODEL];          // linear
__device__ bf16 g_Vt[(long)BATCH * DMODEL * SEQ * 2];       // panels, KC=64
__device__ bf16 g_W[(long)BATCH * SEQ * SEQ * 2];           // panels, KC=64
__device__ float g_pm[BATCH * ICH * SEQ], g_ps[BATCH * ICH * SEQ];
__device__ float g_gm[BATCH * SEQ], g_gi[BATCH * SEQ];

// Panel element addressing (within a 16KB tile)
__device__ __forceinline__ uint32_t off_hi(int r, int kk) {
    return (uint32_t)((r << 7) + ((((kk >> 3) << 4) ^ ((r & 7) << 4)) | ((kk & 7) << 1)));
}
__device__ __forceinline__ uint32_t off_lo(int r, int kk) {
    return (uint32_t)((r << 7) + (((((kk >> 3) + 4) << 4) ^ ((r & 7) << 4)) | ((kk & 7) << 1)));
}

// ---------------------------------------------------------------------------
// PTX helpers
// ---------------------------------------------------------------------------
__device__ __forceinline__ uint32_t smem_u32(const void* p) {
    uint32_t a;
    asm("{ .reg .u64 t; cvta.to.shared.u64 t, %1; cvt.u32.u64 %0, t; }"
        : "=r"(a) : "l"(p));
    return a;
}
__device__ __forceinline__ void ldm_x4(uint32_t* r, uint32_t addr) {
    asm volatile("ldmatrix.sync.aligned.m8n8.x4.shared.b16 {%0,%1,%2,%3}, [%4];"
        : "=r"(r[0]), "=r"(r[1]), "=r"(r[2]), "=r"(r[3]) : "r"(addr));
}
__device__ __forceinline__ void mma16816(float* c, const uint32_t* a, const uint32_t* b) {
    asm volatile(
        "mma.sync.aligned.m16n8k16.row.col.f32.bf16.bf16.f32 "
        "{%0,%1,%2,%3}, {%4,%5,%6,%7}, {%8,%9}, {%0,%1,%2,%3};"
        : "+f"(c[0]), "+f"(c[1]), "+f"(c[2]), "+f"(c[3])
        : "r"(a[0]), "r"(a[1]), "r"(a[2]), "r"(a[3]), "r"(b[0]), "r"(b[1]));
}

#define MBARRIER_INIT(addr, cnt) \
    asm volatile("mbarrier.init.shared.b64 [%0], %1;" \
                 :: "r"((uint32_t)(addr)), "r"((uint32_t)(cnt)) : "memory")
#define MBARRIER_EXPECT_TX(addr, bytes) \
    asm volatile("mbarrier.arrive.expect_tx.shared.b64 _, [%0], %1;" \
                 :: "r"((uint32_t)(addr)), "r"((uint32_t)(bytes)) : "memory")
#define MBARRIER_ARRIVE(addr) \
    asm volatile("mbarrier.arrive.shared.b64 _, [%0];" \
                 :: "r"((uint32_t)(addr)) : "memory")
#define CP_BULK(dst, src, bytes, bar) \
    asm volatile("cp.async.bulk.shared::cta.global.mbarrier::complete_tx::bytes " \
                 "[%0], [%1], %2, [%3];" \
                 :: "r"((uint32_t)(dst)), "l"(src), "r"((uint32_t)(bytes)), \
                    "r"((uint32_t)(bar)) : "memory")
#define FENCE_PROXY_ASYNC() \
    asm volatile("fence.proxy.async.shared::cta;" ::: "memory")

#define MBARRIER_WAIT_PARITY(mbar_smem_addr, phase_parity) do { \
    uint32_t _mbar = (uint32_t)(mbar_smem_addr); \
    uint32_t _parity = (uint32_t)(phase_parity); \
    uint32_t _done; \
    asm volatile( \
        "{\n\t.reg .pred p;\n\t" \
        "mbarrier.try_wait.parity.acquire.cta.shared::cta.b64 p, [%1], %2;\n\t" \
        "selp.b32 %0, 1, 0, p;\n\t}" \
        : "=r"(_done) : "r"(_mbar), "r"(_parity) : "memory"); \
    if (!_done) { \
        asm volatile( \
            "{\n\t.reg .pred P1;\n\t" \
            "WAIT_LOOP_%=:\n\t" \
            "mbarrier.try_wait.parity.acquire.cta.shared::cta.b64 P1, [%0], %1, 0x989680;\n\t" \
            "@P1 bra.uni WAIT_DONE_%=;\n\t" \
            "bra.uni WAIT_LOOP_%=;\n\t" \
            "WAIT_DONE_%=:\n\t}" \
            :: "r"(_mbar), "r"(_parity) : "memory"); \
    } \
} while(0)

// ===========================================================================
// GEMM on panel-layout split bf16, 3-term split (hh+hl+lh).
// Tiles fetched with cp.async.bulk (16KB each) into a 3-stage smem ring with
// full/empty mbarriers (no per-chunk __syncthreads).
// CTA tile 128x128, 256 threads (2 warp_m x 4 warp_n, 64x32 warp tiles).
// ===========================================================================
template<int MODE>
__global__ __launch_bounds__(256, 2)
void gemm_ps(const char* __restrict__ Ab, const char* __restrict__ Bb,
             float alpha, int N, int KC, long sA, long sB, long sC,
             float* __restrict__ Cf,
             float* __restrict__ pm, float* __restrict__ ps,
             const float* __restrict__ bq, const float* __restrict__ bk,
             const float* __restrict__ bv,
             bf16* __restrict__ Qp, bf16* __restrict__ Kp,
             bf16* __restrict__ Vhi, bf16* __restrict__ Vlo)
{
    const char* A = Ab + (long)blockIdx.z * sA;
    const char* B = Bb + (long)blockIdx.z * sB;
    const long zc = (long)blockIdx.z * sC;
    const int bm = blockIdx.y * BM;
    const int bn = blockIdx.x * BN;
    const int tid = threadIdx.x;
    const int wid = tid >> 5, lane = tid & 31;
    const int warp_m = wid & 1;
    const int warp_n = wid >> 1;

    extern __shared__ __align__(16) char dynsmem[];
    const uint32_t sbase = smem_u32(dynsmem);
    __shared__ __align__(8) unsigned long long s_bar[NSTAGE];
    __shared__ __align__(8) unsigned long long s_emp[NSTAGE];
    const uint32_t bar0 = smem_u32(s_bar);
    const uint32_t emp0 = smem_u32(s_emp);

    if (tid == 0) {
        #pragma unroll
        for (int s = 0; s < NSTAGE; s++) {
            MBARRIER_INIT(bar0 + s * 8, 1);
            MBARRIER_INIT(emp0 + s * 8, 256);
        }
        FENCE_PROXY_ASYNC();
    }
    __syncthreads();

    float acc[4][4][4] = {};

    const int a_row = warp_m * 64 + (lane & 15);
    const uint32_t a_k = (uint32_t)(((lane >> 4) * 8) * 2);
    const int b_row = warp_n * 32 + (lane & 7) + ((lane >> 4) * 8);
    const uint32_t b_k = (uint32_t)((((lane >> 3) & 1) * 8) * 2);
    const uint32_t swz = (uint32_t)((lane & 7) << 4);

    const int nch = KC;
    const long pA = (long)blockIdx.y * KC;   // A panel row-block
    const long pB = (long)blockIdx.x * KC;

    // Prologue: issue chunks 0 and 1 (chunk 2 issued at c=0 in the loop)
    if (tid == 0) {
        #pragma unroll
        for (int c = 0; c < 2; c++) {
            const uint32_t bar = bar0 + c * 8;
            MBARRIER_EXPECT_TX(bar, 2 * TILE_B);
            CP_BULK(sbase + c * STAGE_B,          A + ((pA + c) << 14), TILE_B, bar);
            CP_BULK(sbase + c * STAGE_B + TILE_B, B + ((pB + c) << 14), TILE_B, bar);
        }
    }

    for (int c = 0; c < nch; c++) {
        // Producer: issue chunk c+2 into stage (c+2)%3 once its previous
        // consumers have all arrived on the stage's empty barrier.
        if (tid == 0 && c + 2 < nch) {
            const int s = (c + 2) % NSTAGE;
            if (c + 2 >= NSTAGE)
                MBARRIER_WAIT_PARITY(emp0 + s * 8, (((c + 2) / NSTAGE) - 1) & 1);
            const uint32_t bar = bar0 + s * 8;
            MBARRIER_EXPECT_TX(bar, 2 * TILE_B);
            CP_BULK(sbase + s * STAGE_B,          A + ((pA + c + 2) << 14), TILE_B, bar);
            CP_BULK(sbase + s * STAGE_B + TILE_B, B + ((pB + c + 2) << 14), TILE_B, bar);
        }

        const int st = c % NSTAGE;
        MBARRIER_WAIT_PARITY(bar0 + st * 8, (c / NSTAGE) & 1);

        const uint32_t uA = sbase + st * STAGE_B;
        const uint32_t uB = uA + TILE_B;

        #pragma unroll
        for (int ks = 0; ks < 2; ks++) {
            const uint32_t akh = ((a_k + ks * 32) ^ swz);
            const uint32_t akl = ((a_k + ks * 32 + 64) ^ swz);
            const uint32_t bkh = ((b_k + ks * 32) ^ swz);
            const uint32_t bkl = ((b_k + ks * 32 + 64) ^ swz);
            uint32_t afh[4][4], afl[4][4], bfh[2][4], bfl[2][4];
            // Load afh, bfh, bfl up front -> LDSM latency hides under hh MMAs
            #pragma unroll
            for (int mi = 0; mi < 4; mi++)
                ldm_x4(afh[mi], uA + (uint32_t)((a_row + mi * 16) * 128) + akh);
            #pragma unroll
            for (int nb2 = 0; nb2 < 2; nb2++)
                ldm_x4(bfh[nb2], uB + (uint32_t)((b_row + nb2 * 16) * 128) + bkh);
            #pragma unroll
            for (int nb2 = 0; nb2 < 2; nb2++)
                ldm_x4(bfl[nb2], uB + (uint32_t)((b_row + nb2 * 16) * 128) + bkl);
            #pragma unroll
            for (int mi = 0; mi < 4; mi++)
                #pragma unroll
                for (int ni = 0; ni < 4; ni++)
                    mma16816(acc[mi][ni], afh[mi], &bfh[ni >> 1][(ni & 1) * 2]);
            #pragma unroll
            for (int mi = 0; mi < 4; mi++)
                ldm_x4(afl[mi], uA + (uint32_t)((a_row + mi * 16) * 128) + akl);
            #pragma unroll
            for (int mi = 0; mi < 4; mi++)
                #pragma unroll
                for (int ni = 0; ni < 4; ni++)
                    mma16816(acc[mi][ni], afh[mi], &bfl[ni >> 1][(ni & 1) * 2]);
            #pragma unroll
            for (int mi = 0; mi < 4; mi++)
                #pragma unroll
                for (int ni = 0; ni < 4; ni++)
                    mma16816(acc[mi][ni], afl[mi], &bfh[ni >> 1][(ni & 1) * 2]);
        }
        // All smem reads for this chunk done (LDSM is synchronous) -> release
        MBARRIER_ARRIVE(emp0 + st * 8);
    }

    // ---------------- Epilogue ----------------
    const int erow = lane >> 2;
    const int ecol = 2 * (lane & 3);

    if (MODE == MODE_PROJ) {
        #pragma unroll
        for (int mi = 0; mi < 4; mi++) {
            #pragma unroll
            for (int ni = 0; ni < 4; ni++) {
                const int col = bn + warp_n * 32 + ni * 8 + ecol;
                const int sel = col >> 9;
                const int nn = col & 511;
                const float* bp = (sel == 0) ? bq : (sel == 1) ? bk : bv;
                const float bx = bp[nn], by = bp[nn + 1];
                #pragma unroll
                for (int h = 0; h < 2; h++) {
                    const int row = bm + warp_m * 64 + mi * 16 + erow + h * 8;
                    float vx = acc[mi][ni][2 * h + 0] + bx;
                    float vy = acc[mi][ni][2 * h + 1] + by;
                    bf162 hh = __floats2bfloat162_rn(vx, vy);
                    float2 hf = __bfloat1622float2(hh);
                    bf162 ll = __floats2bfloat162_rn(vx - hf.x, vy - hf.y);
                    if (sel == 2) {
                        const long off = (long)row * DMODEL + nn;
                        *(bf162*)(Vhi + off) = hh;
                        *(bf162*)(Vlo + off) = ll;
                    } else {
                        char* basep = (char*)((sel == 0) ? Qp : Kp);
                        const long pnl = (long)(row >> 7) * 16 + (nn >> 5);
                        const int r = row & 127, kk = nn & 31;
                        *(bf162*)(basep + (pnl << 14) + off_hi(r, kk)) = hh;
                        *(bf162*)(basep + (pnl << 14) + off_lo(r, kk)) = ll;
                    }
                }
            }
        }
    } else {
        #pragma unroll
        for (int mi = 0; mi < 4; mi++) {
            #pragma unroll
            for (int ni = 0; ni < 4; ni++) {
                const int col = bn + warp_n * 32 + ni * 8 + ecol;
                #pragma unroll
                for (int h = 0; h < 2; h++) {
                    const int row = bm + warp_m * 64 + mi * 16 + erow + h * 8;
                    float2 v;
                    v.x = acc[mi][ni][2 * h + 0] * alpha;
                    v.y = acc[mi][ni][2 * h + 1] * alpha;
                    *(float2*)(Cf + zc + (long)row * N + col) = v;
                }
            }
        }
    }

    if (MODE == MODE_SCORES) {
        __syncthreads();                             // smem reuse after loop
        float* red_m = (float*)dynsmem;              // [2][128]
        float* red_s = (float*)(dynsmem + 1024);     // [2][128]

        float lm[4][2];
        #pragma unroll
        for (int ni = 0; ni < 4; ni++)
            #pragma unroll
            for (int cc = 0; cc < 2; cc++) {
                float m = -INFINITY;
                #pragma unroll
                for (int mi = 0; mi < 4; mi++)
                    #pragma unroll
                    for (int h = 0; h < 2; h++)
                        m = fmaxf(m, acc[mi][ni][2 * h + cc] * alpha);
                lm[ni][cc] = m;
            }
        #pragma unroll
        for (int off = 4; off < 32; off <<= 1)
            #pragma unroll
            for (int ni = 0; ni < 4; ni++)
                #pragma unroll
                for (int cc = 0; cc < 2; cc++)
                    lm[ni][cc] = fmaxf(lm[ni][cc],
                        __shfl_xor_sync(0xffffffffu, lm[ni][cc], off));
        if (lane < 4) {
            #pragma unroll
            for (int ni = 0; ni < 4; ni++)
                #pragma unroll
                for (int cc = 0; cc < 2; cc++)
                    red_m[warp_m * 128 + warp_n * 32 + ni * 8 + 2 * lane + cc] = lm[ni][cc];
        }
        __syncthreads();

        float cmax[4][2], lsum[4][2];
        #pragma unroll
        for (int ni = 0; ni < 4; ni++)
            #pragma unroll
            for (int cc = 0; cc < 2; cc++) {
                const int cl = warp_n * 32 + ni * 8 + ecol + cc;
                cmax[ni][cc] = fmaxf(red_m[cl], red_m[128 + cl]);
                float s = 0.f;
                #pragma unroll
                for (int mi = 0; mi < 4; mi++)
                    #pragma unroll
                    for (int h = 0; h < 2; h++)
                        s += __expf(acc[mi][ni][2 * h + cc] * alpha - cmax[ni][cc]);
                lsum[ni][cc] = s;
            }
        #pragma unroll
        for (int off = 4; off < 32; off <<= 1)
            #pragma unroll
            for (int ni = 0; ni < 4; ni++)
                #pragma unroll
                for (int cc = 0; cc < 2; cc++)
                    lsum[ni][cc] += __shfl_xor_sync(0xffffffffu, lsum[ni][cc], off);
        if (lane < 4) {
            #pragma unroll
            for (int ni = 0; ni < 4; ni++)
                #pragma unroll
                for (int cc = 0; cc < 2; cc++)
                    red_s[warp_m * 128 + warp_n * 32 + ni * 8 + 2 * lane + cc] = lsum[ni][cc];
        }
        __syncthreads();

        if (warp_m == 0 && lane < 4) {
            const long pbase = ((long)blockIdx.z * ICH + blockIdx.y) * SEQ + bn;
            #pragma unroll
            for (int ni = 0; ni < 4; ni++)
                #pragma unroll
                for (int cc = 0; cc < 2; cc++) {
                    const int cl = warp_n * 32 + ni * 8 + 2 * lane + cc;
                    pm[pbase + cl] = cmax[ni][cc];
                    ps[pbase + cl] = red_s[cl] + red_s[128 + cl];
                }
        }
    }
}

// ---------------------------------------------------------------------------
// x fp32 -> split panels (4 elems per thread, same 16B chunk)
// ---------------------------------------------------------------------------
__global__ void split_x(const float* __restrict__ src, bf16* __restrict__ dst)
{
    const long i = (long)blockIdx.x * blockDim.x + threadIdx.x;
    const long e4 = i * 4;
    const int row = (int)(e4 >> 9);
    const int k = (int)(e4 & 511);
    float4 a = ((const float4*)src)[i];
    bf162 h0 = __floats2bfloat162_rn(a.x, a.y);
    bf162 h1 = __floats2bfloat162_rn(a.z, a.w);
    float2 f0 = __bfloat1622float2(h0);
    float2 f1 = __bfloat1622float2(h1);
    bf162 l0 = __floats2bfloat162_rn(a.x - f0.x, a.y - f0.y);
    bf162 l1 = __floats2bfloat162_rn(a.z - f1.x, a.w - f1.y);
    const long pnl = (long)(row >> 7) * 16 + (k >> 5);
    const int r = row & 127, kk = k & 31;
    char* base = (char*)dst + (pnl << 14);
    union { bf162 v[2]; uint2 u; } uh, ul;
    uh.v[0] = h0; uh.v[1] = h1;
    ul.v[0] = l0; ul.v[1] = l1;
    *(uint2*)(base + off_hi(r, kk)) = uh.u;
    *(uint2*)(base + off_lo(r, kk)) = ul.u;
}

// ---------------------------------------------------------------------------
// W fp32 [K][N] -> Wt split panels [n][k]; grid.z selects W
// ---------------------------------------------------------------------------
__global__ void transpose_split_w(const float* __restrict__ W0,
                                  const float* __restrict__ W1,
                                  const float* __restrict__ W2,
                                  bf16* __restrict__ T)
{
    __shared__ float tile[32][33];
    const int w = blockIdx.z;
    const float* W = (w == 0) ? W0 : (w == 1) ? W1 : W2;
    const int k0 = blockIdx.y * 32, n0 = blockIdx.x * 32;
    const int tx = threadIdx.x, ty = threadIdx.y;
    #pragma unroll
    for (int yy = 0; yy < 32; yy += 8)
        tile[ty + yy][tx] = W[(long)(k0 + ty + yy) * DMODEL + n0 + tx];
    __syncthreads();
    #pragma unroll
    for (int yy = 0; yy < 32; yy += 8) {
        float v = tile[tx][ty + yy];
        bf16 h = __float2bfloat16_rn(v);
        bf16 l = __float2bfloat16_rn(v - __bfloat162float(h));
        const int ng = w * DMODEL + n0 + ty + yy;
        const int k = k0 + tx;
        const long pnl = (long)(ng >> 7) * 16 + (k >> 5);
        char* base = (char*)T + (pnl << 14);
        *(bf16*)(base + off_hi(ng & 127, k & 31)) = h;
        *(bf16*)(base + off_lo(ng & 127, k & 31)) = l;
    }
}

// ---------------------------------------------------------------------------
// Linear split V -> Vt panels [b][e rows][j], KC=64
// ---------------------------------------------------------------------------
__global__ void transpose_v(const bf16* __restrict__ Vhi, const bf16* __restrict__ Vlo,
                            bf16* __restrict__ Vt)
{
    __shared__ bf16 th[32][33], tl[32][33];
    const long b = blockIdx.z;
    const int e0 = blockIdx.x * 32, n0 = blockIdx.y * 32;
    const int tx = threadIdx.x, ty = threadIdx.y;
    #pragma unroll
    for (int yy = 0; yy < 32; yy += 8) {
        const long src = (b * SEQ + n0 + ty + yy) * DMODEL + e0 + tx;
        th[ty + yy][tx] = Vhi[src];
        tl[ty + yy][tx] = Vlo[src];
    }
    __syncthreads();
    char* bbase = (char*)Vt + b * ((long)DMODEL * SEQ * 4);
    #pragma unroll
    for (int yy = 0; yy < 32; yy += 8) {
        const int e = e0 + ty + yy;
        const int j = n0 + tx;
        const long pnl = (long)(e >> 7) * 64 + (j >> 5);
        char* base = bbase + (pnl << 14);
        *(bf16*)(base + off_hi(e & 127, j & 31)) = th[tx][ty + yy];
        *(bf16*)(base + off_lo(e & 127, j & 31)) = tl[tx][ty + yy];
    }
}

// ---------------------------------------------------------------------------
// Softmax combine + normalize; pass3 writes fp32 output AND W panels (KC=64)
// ---------------------------------------------------------------------------
__global__ void sm_pass2(const float* __restrict__ pm, const float* __restrict__ ps,
                         float* __restrict__ gm, float* __restrict__ gi)
{
    const int j = blockIdx.x * blockDim.x + threadIdx.x;
    const long b = blockIdx.y;
    float m = -INFINITY;
    #pragma unroll
    for (int ic = 0; ic < ICH; ic++)
        m = fmaxf(m, pm[(b * ICH + ic) * SEQ + j]);
    float s = 0.0f;
    #pragma unroll
    for (int ic = 0; ic < ICH; ic++)
        s += ps[(b * ICH + ic) * SEQ + j] * __expf(pm[(b * ICH + ic) * SEQ + j] - m);
    gm[b * SEQ + j] = m;
    gi[b * SEQ + j] = 1.0f / s;
}

__global__ void sm_pass3(float* __restrict__ S,
                         const float* __restrict__ gm, const float* __restrict__ gi,
                         bf16* __restrict__ Wp)
{
    const int j4 = (blockIdx.x * blockDim.x + threadIdx.x) * 4;
    const int i = blockIdx.y;
    const long b = blockIdx.z;
    const long off = b * (long)SEQ * SEQ + (long)i * SEQ + j4;
    float4 x = *(const float4*)(S + off);
    float4 m = *(const float4*)(gm + b * SEQ + j4);
    float4 v = *(const float4*)(gi + b * SEQ + j4);
    float4 w;
    w.x = __expf(x.x - m.x) * v.x;
    w.y = __expf(x.y - m.y) * v.y;
    w.z = __expf(x.z - m.z) * v.z;
    w.w = __expf(x.w - m.w) * v.w;
    *(float4*)(S + off) = w;
    bf162 h0 = __floats2bfloat162_rn(w.x, w.y);
    bf162 h1 = __floats2bfloat162_rn(w.z, w.w);
    float2 f0 = __bfloat1622float2(h0);
    float2 f1 = __bfloat1622float2(h1);
    bf162 l0 = __floats2bfloat162_rn(w.x - f0.x, w.y - f0.y);
    bf162 l1 = __floats2bfloat162_rn(w.z - f1.x, w.w - f1.y);
    char* bbase = (char*)Wp + b * ((long)SEQ * SEQ * 4);
    const long pnl = (long)(i >> 7) * 64 + (j4 >> 5);
    char* base = bbase + (pnl << 14);
    const int r = i & 127, kk = j4 & 31;
    union { bf162 v[2]; uint2 u; } uh, ul;
    uh.v[0] = h0; uh.v[1] = h1;
    ul.v[0] = l0; ul.v[1] = l1;
    *(uint2*)(base + off_hi(r, kk)) = uh.u;
    *(uint2*)(base + off_lo(r, kk)) = ul.u;
}

// ---------------------------------------------------------------------------
// kernel_launch — fork/join a second stream for independent prep kernels
// ---------------------------------------------------------------------------
extern "C" void kernel_launch(void* const* d_in, const int* in_sizes, int n_in,
                              void* d_out, int out_size)
{
    const float* x  = (const float*)d_in[0];
    const float* Wq = (const float*)d_in[1];
    const float* bq = (const float*)d_in[2];
    const float* Wk = (const float*)d_in[3];
    const float* bk = (const float*)d_in[4];
    const float* Wv = (const float*)d_in[5];
    const float* bv = (const float*)d_in[6];

    float* out     = (float*)d_out;
    float* weights = out + (long)BATCH * SEQ * DMODEL;

    bf16 *xp, *Wtp, *Qp, *Kp, *Vhi, *Vlo, *Vtp, *Wp;
    float *pm, *ps, *gm, *gi;
    cudaGetSymbolAddress((void**)&xp, g_x);
    cudaGetSymbolAddress((void**)&Wtp, g_Wt);
    cudaGetSymbolAddress((void**)&Qp, g_Q);
    cudaGetSymbolAddress((void**)&Kp, g_K);
    cudaGetSymbolAddress((void**)&Vhi, g_Vhi);
    cudaGetSymbolAddress((void**)&Vlo, g_Vlo);
    cudaGetSymbolAddress((void**)&Vtp, g_Vt);
    cudaGetSymbolAddress((void**)&Wp, g_W);
    cudaGetSymbolAddress((void**)&pm, g_pm);
    cudaGetSymbolAddress((void**)&ps, g_ps);
    cudaGetSymbolAddress((void**)&gm, g_gm);
    cudaGetSymbolAddress((void**)&gi, g_gi);

    static bool init_done = false;
    static cudaStream_t s2;
    static cudaEvent_t evF, evW, evP, evV;
    if (!init_done) {
        cudaFuncSetAttribute(gemm_ps<MODE_PROJ>,
                             cudaFuncAttributeMaxDynamicSharedMemorySize, DYN_SMEM);
        cudaFuncSetAttribute(gemm_ps<MODE_SCORES>,
                             cudaFuncAttributeMaxDynamicSharedMemorySize, DYN_SMEM);
        cudaFuncSetAttribute(gemm_ps<MODE_AV>,
                             cudaFuncAttributeMaxDynamicSharedMemorySize, DYN_SMEM);
        cudaStreamCreateWithFlags(&s2, cudaStreamNonBlocking);
        cudaEventCreateWithFlags(&evF, cudaEventDisableTiming);
        cudaEventCreateWithFlags(&evW, cudaEventDisableTiming);
        cudaEventCreateWithFlags(&evP, cudaEventDisableTiming);
        cudaEventCreateWithFlags(&evV, cudaEventDisableTiming);
        init_done = true;
    }

    const dim3 blk(256);

    // ---- Fork: s2 joins the capture DAG behind nothing yet ----
    cudaEventRecord(evF, 0);
    cudaStreamWaitEvent(s2, evF, 0);

    // 0) inputs -> panel layout (x on stream 0, W transpose on s2)
    split_x<<<(BATCH * SEQ * DMODEL / 4) / 256, blk>>>(x, xp);
    {
        dim3 g(16, 16, 3), b(32, 8);
        transpose_split_w<<<g, b, 0, s2>>>(Wq, Wk, Wv, Wtp);
    }
    cudaEventRecord(evW, s2);
    cudaStreamWaitEvent(0, evW, 0);

    // 1) fused QKV projection: A = x panels, B = Wt panels (KC = 16)
    {
        dim3 grid(3 * DMODEL / BN, (BATCH * SEQ) / BM, 1);
        gemm_ps<MODE_PROJ><<<grid, blk, DYN_SMEM>>>(
            (const char*)xp, (const char*)Wtp, 1.0f, 3 * DMODEL, DMODEL / 32,
            0, 0, 0, nullptr, nullptr, nullptr, bq, bk, bv, Qp, Kp, Vhi, Vlo);
    }

    // Fork after proj: transpose_v on s2 runs concurrent with scores+softmax
    cudaEventRecord(evP, 0);
    cudaStreamWaitEvent(s2, evP, 0);
    {
        dim3 g(DMODEL / 32, SEQ / 32, BATCH), b(32, 8);
        transpose_v<<<g, b, 0, s2>>>(Vhi, Vlo, Vtp);
    }
    cudaEventRecord(evV, s2);

    // 2) scores = scale * Q @ K^T -> weights fp32 + softmax partials (KC = 16)
    {
        const float scale = 1.0f / sqrtf((float)DMODEL);
        dim3 grid(SEQ / BN, SEQ / BM, BATCH);
        gemm_ps<MODE_SCORES><<<grid, blk, DYN_SMEM>>>(
            (const char*)Qp, (const char*)Kp, scale, SEQ, DMODEL / 32,
            (long)SEQ * DMODEL * 4, (long)SEQ * DMODEL * 4, (long)SEQ * SEQ,
            weights, pm, ps, nullptr, nullptr, nullptr,
            nullptr, nullptr, nullptr, nullptr);
    }

    // 3) softmax combine + normalize (pass3 emits W panels)
    {
        dim3 g2(SEQ / 256, BATCH);
        sm_pass2<<<g2, blk>>>(pm, ps, gm, gi);
        dim3 g3(SEQ / (256 * 4), SEQ, BATCH);
        sm_pass3<<<g3, blk>>>(weights, gm, gi, Wp);
    }

    // Join: AV needs both pass3 (stream 0) and transpose_v (s2)
    cudaStreamWaitEvent(0, evV, 0);

    // 4) out = weights @ V: A = W panels, B = Vt panels (KC = 64)
    {
        dim3 grid(DMODEL / BN, SEQ / BM, BATCH);
        gemm_ps<MODE_AV><<<grid, blk, DYN_SMEM>>>(
            (const char*)Wp, (const char*)Vtp, 1.0f, DMODEL, SEQ / 32,
            (long)SEQ * SEQ * 4, (long)DMODEL * SEQ * 4, (long)SEQ * DMODEL,
            out, nullptr, nullptr, nullptr, nullptr, nullptr,
            nullptr, nullptr, nullptr, nullptr);
    }
}

// round 15
// speedup vs baseline: 1.2289x; 1.0667x over previous
#include <cuda_runtime.h>
#include <cuda_bf16.h>
#include <math.h>
#include <stdint.h>

// Problem constants
#define BATCH 8
#define SEQ   2048
#define DMODEL 512

#define BM 128
#define BN 128
// tile: 128 rows x 128B (hi bytes [0,64), lo [64,128)), XOR-swizzled, = 16KB
#define TILE_B  16384
#define STAGE_B (2 * TILE_B)
#define NSTAGE  3
#define DYN_SMEM (NSTAGE * STAGE_B)   // 96 KB

#define ICH 16
#define MODE_PROJ   0
#define MODE_SCORES 1
#define MODE_AV     2

typedef __nv_bfloat16 bf16;
typedef __nv_bfloat162 bf162;

// ---------------------------------------------------------------------------
// Device scratch: panel (tile-major, pre-swizzled) arrays hold hi+lo combined.
// ---------------------------------------------------------------------------
__device__ bf16 g_x[(long)BATCH * SEQ * DMODEL * 2];        // panels, KC=16
__device__ bf16 g_Wt[3L * DMODEL * DMODEL * 2];             // panels, KC=16
__device__ bf16 g_Q[(long)BATCH * SEQ * DMODEL * 2];        // panels, KC=16
__device__ bf16 g_K[(long)BATCH * SEQ * DMODEL * 2];        // panels, KC=16
__device__ bf16 g_Vhi[(long)BATCH * SEQ * DMODEL];          // linear
__device__ bf16 g_Vlo[(long)BATCH * SEQ * DMODEL];          // linear
__device__ bf16 g_Vt[(long)BATCH * DMODEL * SEQ * 2];       // panels, KC=64
__device__ bf16 g_W[(long)BATCH * SEQ * SEQ * 2];           // panels, KC=64
__device__ float g_pm[BATCH * ICH * SEQ], g_ps[BATCH * ICH * SEQ];
__device__ float g_gm[BATCH * SEQ], g_gi[BATCH * SEQ];

// Panel element addressing (within a 16KB tile)
__device__ __forceinline__ uint32_t off_hi(int r, int kk) {
    return (uint32_t)((r << 7) + ((((kk >> 3) << 4) ^ ((r & 7) << 4)) | ((kk & 7) << 1)));
}
__device__ __forceinline__ uint32_t off_lo(int r, int kk) {
    return (uint32_t)((r << 7) + (((((kk >> 3) + 4) << 4) ^ ((r & 7) << 4)) | ((kk & 7) << 1)));
}

// ---------------------------------------------------------------------------
// PTX helpers
// ---------------------------------------------------------------------------
__device__ __forceinline__ uint32_t smem_u32(const void* p) {
    uint32_t a;
    asm("{ .reg .u64 t; cvta.to.shared.u64 t, %1; cvt.u32.u64 %0, t; }"
        : "=r"(a) : "l"(p));
    return a;
}
__device__ __forceinline__ void ldm_x4(uint32_t* r, uint32_t addr) {
    asm volatile("ldmatrix.sync.aligned.m8n8.x4.shared.b16 {%0,%1,%2,%3}, [%4];"
        : "=r"(r[0]), "=r"(r[1]), "=r"(r[2]), "=r"(r[3]) : "r"(addr));
}
__device__ __forceinline__ void mma16816(float* c, const uint32_t* a, const uint32_t* b) {
    asm volatile(
        "mma.sync.aligned.m16n8k16.row.col.f32.bf16.bf16.f32 "
        "{%0,%1,%2,%3}, {%4,%5,%6,%7}, {%8,%9}, {%0,%1,%2,%3};"
        : "+f"(c[0]), "+f"(c[1]), "+f"(c[2]), "+f"(c[3])
        : "r"(a[0]), "r"(a[1]), "r"(a[2]), "r"(a[3]), "r"(b[0]), "r"(b[1]));
}

#define MBARRIER_INIT(addr, cnt) \
    asm volatile("mbarrier.init.shared.b64 [%0], %1;" \
                 :: "r"((uint32_t)(addr)), "r"((uint32_t)(cnt)) : "memory")
#define MBARRIER_EXPECT_TX(addr, bytes) \
    asm volatile("mbarrier.arrive.expect_tx.shared.b64 _, [%0], %1;" \
                 :: "r"((uint32_t)(addr)), "r"((uint32_t)(bytes)) : "memory")
#define MBARRIER_ARRIVE(addr) \
    asm volatile("mbarrier.arrive.shared.b64 _, [%0];" \
                 :: "r"((uint32_t)(addr)) : "memory")
#define CP_BULK(dst, src, bytes, bar) \
    asm volatile("cp.async.bulk.shared::cta.global.mbarrier::complete_tx::bytes " \
                 "[%0], [%1], %2, [%3];" \
                 :: "r"((uint32_t)(dst)), "l"(src), "r"((uint32_t)(bytes)), \
                    "r"((uint32_t)(bar)) : "memory")
#define FENCE_PROXY_ASYNC() \
    asm volatile("fence.proxy.async.shared::cta;" ::: "memory")

#define MBARRIER_WAIT_PARITY(mbar_smem_addr, phase_parity) do { \
    uint32_t _mbar = (uint32_t)(mbar_smem_addr); \
    uint32_t _parity = (uint32_t)(phase_parity); \
    uint32_t _done; \
    asm volatile( \
        "{\n\t.reg .pred p;\n\t" \
        "mbarrier.try_wait.parity.acquire.cta.shared::cta.b64 p, [%1], %2;\n\t" \
        "selp.b32 %0, 1, 0, p;\n\t}" \
        : "=r"(_done) : "r"(_mbar), "r"(_parity) : "memory"); \
    if (!_done) { \
        asm volatile( \
            "{\n\t.reg .pred P1;\n\t" \
            "WAIT_LOOP_%=:\n\t" \
            "mbarrier.try_wait.parity.acquire.cta.shared::cta.b64 P1, [%0], %1, 0x989680;\n\t" \
            "@P1 bra.uni WAIT_DONE_%=;\n\t" \
            "bra.uni WAIT_LOOP_%=;\n\t" \
            "WAIT_DONE_%=:\n\t}" \
            :: "r"(_mbar), "r"(_parity) : "memory"); \
    } \
} while(0)

// ===========================================================================
// GEMM on panel-layout split bf16, 3-term split (hh+hl+lh).
// Tiles fetched with cp.async.bulk (16KB each) into a 3-stage smem ring with
// full/empty mbarriers (no per-chunk __syncthreads).
// CTA tile 128x128, 256 threads (2 warp_m x 4 warp_n, 64x32 warp tiles).
// ===========================================================================
template<int MODE>
__global__ __launch_bounds__(256, 2)
void gemm_ps(const char* __restrict__ Ab, const char* __restrict__ Bb,
             float alpha, int N, int KC, long sA, long sB, long sC,
             float* __restrict__ Cf,
             float* __restrict__ pm, float* __restrict__ ps,
             const float* __restrict__ bq, const float* __restrict__ bk,
             const float* __restrict__ bv,
             bf16* __restrict__ Qp, bf16* __restrict__ Kp,
             bf16* __restrict__ Vhi, bf16* __restrict__ Vlo)
{
    const char* A = Ab + (long)blockIdx.z * sA;
    const char* B = Bb + (long)blockIdx.z * sB;
    const long zc = (long)blockIdx.z * sC;
    const int bm = blockIdx.y * BM;
    const int bn = blockIdx.x * BN;
    const int tid = threadIdx.x;
    const int wid = tid >> 5, lane = tid & 31;
    const int warp_m = wid & 1;
    const int warp_n = wid >> 1;

    extern __shared__ __align__(16) char dynsmem[];
    const uint32_t sbase = smem_u32(dynsmem);
    __shared__ __align__(8) unsigned long long s_bar[NSTAGE];
    __shared__ __align__(8) unsigned long long s_emp[NSTAGE];
    const uint32_t bar0 = smem_u32(s_bar);
    const uint32_t emp0 = smem_u32(s_emp);

    if (tid == 0) {
        #pragma unroll
        for (int s = 0; s < NSTAGE; s++) {
            MBARRIER_INIT(bar0 + s * 8, 1);
            MBARRIER_INIT(emp0 + s * 8, 256);
        }
        FENCE_PROXY_ASYNC();
    }
    __syncthreads();

    float acc[4][4][4] = {};

    const int a_row = warp_m * 64 + (lane & 15);
    const uint32_t a_k = (uint32_t)(((lane >> 4) * 8) * 2);
    const int b_row = warp_n * 32 + (lane & 7) + ((lane >> 4) * 8);
    const uint32_t b_k = (uint32_t)((((lane >> 3) & 1) * 8) * 2);
    const uint32_t swz = (uint32_t)((lane & 7) << 4);

    const int nch = KC;
    const long pA = (long)blockIdx.y * KC;   // A panel row-block
    const long pB = (long)blockIdx.x * KC;

    // Prologue: issue chunks 0 and 1 (chunk 2 issued at c=0 in the loop)
    if (tid == 0) {
        #pragma unroll
        for (int c = 0; c < 2; c++) {
            const uint32_t bar = bar0 + c * 8;
            MBARRIER_EXPECT_TX(bar, 2 * TILE_B);
            CP_BULK(sbase + c * STAGE_B,          A + ((pA + c) << 14), TILE_B, bar);
            CP_BULK(sbase + c * STAGE_B + TILE_B, B + ((pB + c) << 14), TILE_B, bar);
        }
    }

    for (int c = 0; c < nch; c++) {
        // Producer: issue chunk c+2 into stage (c+2)%3 once its previous
        // consumers have all arrived on the stage's empty barrier.
        if (tid == 0 && c + 2 < nch) {
            const int s = (c + 2) % NSTAGE;
            if (c + 2 >= NSTAGE)
                MBARRIER_WAIT_PARITY(emp0 + s * 8, (((c + 2) / NSTAGE) - 1) & 1);
            const uint32_t bar = bar0 + s * 8;
            MBARRIER_EXPECT_TX(bar, 2 * TILE_B);
            CP_BULK(sbase + s * STAGE_B,          A + ((pA + c + 2) << 14), TILE_B, bar);
            CP_BULK(sbase + s * STAGE_B + TILE_B, B + ((pB + c + 2) << 14), TILE_B, bar);
        }

        const int st = c % NSTAGE;
        MBARRIER_WAIT_PARITY(bar0 + st * 8, (c / NSTAGE) & 1);

        const uint32_t uA = sbase + st * STAGE_B;
        const uint32_t uB = uA + TILE_B;

        #pragma unroll
        for (int ks = 0; ks < 2; ks++) {
            const uint32_t akh = ((a_k + ks * 32) ^ swz);
            const uint32_t akl = ((a_k + ks * 32 + 64) ^ swz);
            const uint32_t bkh = ((b_k + ks * 32) ^ swz);
            const uint32_t bkl = ((b_k + ks * 32 + 64) ^ swz);
            uint32_t afh[4][4], afl[4][4], bfh[2][4], bfl[2][4];
            // Load afh, bfh, bfl up front -> LDSM latency hides under hh MMAs
            #pragma unroll
            for (int mi = 0; mi < 4; mi++)
                ldm_x4(afh[mi], uA + (uint32_t)((a_row + mi * 16) * 128) + akh);
            #pragma unroll
            for (int nb2 = 0; nb2 < 2; nb2++)
                ldm_x4(bfh[nb2], uB + (uint32_t)((b_row + nb2 * 16) * 128) + bkh);
            #pragma unroll
            for (int nb2 = 0; nb2 < 2; nb2++)
                ldm_x4(bfl[nb2], uB + (uint32_t)((b_row + nb2 * 16) * 128) + bkl);
            #pragma unroll
            for (int mi = 0; mi < 4; mi++)
                #pragma unroll
                for (int ni = 0; ni < 4; ni++)
                    mma16816(acc[mi][ni], afh[mi], &bfh[ni >> 1][(ni & 1) * 2]);
            #pragma unroll
            for (int mi = 0; mi < 4; mi++)
                ldm_x4(afl[mi], uA + (uint32_t)((a_row + mi * 16) * 128) + akl);
            #pragma unroll
            for (int mi = 0; mi < 4; mi++)
                #pragma unroll
                for (int ni = 0; ni < 4; ni++)
                    mma16816(acc[mi][ni], afh[mi], &bfl[ni >> 1][(ni & 1) * 2]);
            #pragma unroll
            for (int mi = 0; mi < 4; mi++)
                #pragma unroll
                for (int ni = 0; ni < 4; ni++)
                    mma16816(acc[mi][ni], afl[mi], &bfh[ni >> 1][(ni & 1) * 2]);
        }
        // All smem reads for this chunk done (LDSM is synchronous) -> release
        MBARRIER_ARRIVE(emp0 + st * 8);
    }

    // ---------------- Epilogue ----------------
    const int erow = lane >> 2;
    const int ecol = 2 * (lane & 3);

    if (MODE == MODE_PROJ) {
        #pragma unroll
        for (int mi = 0; mi < 4; mi++) {
            #pragma unroll
            for (int ni = 0; ni < 4; ni++) {
                const int col = bn + warp_n * 32 + ni * 8 + ecol;
                const int sel = col >> 9;
                const int nn = col & 511;
                const float* bp = (sel == 0) ? bq : (sel == 1) ? bk : bv;
                const float bx = bp[nn], by = bp[nn + 1];
                #pragma unroll
                for (int h = 0; h < 2; h++) {
                    const int row = bm + warp_m * 64 + mi * 16 + erow + h * 8;
                    float vx = acc[mi][ni][2 * h + 0] + bx;
                    float vy = acc[mi][ni][2 * h + 1] + by;
                    bf162 hh = __floats2bfloat162_rn(vx, vy);
                    float2 hf = __bfloat1622float2(hh);
                    bf162 ll = __floats2bfloat162_rn(vx - hf.x, vy - hf.y);
                    if (sel == 2) {
                        const long off = (long)row * DMODEL + nn;
                        *(bf162*)(Vhi + off) = hh;
                        *(bf162*)(Vlo + off) = ll;
                    } else {
                        char* basep = (char*)((sel == 0) ? Qp : Kp);
                        const long pnl = (long)(row >> 7) * 16 + (nn >> 5);
                        const int r = row & 127, kk = nn & 31;
                        *(bf162*)(basep + (pnl << 14) + off_hi(r, kk)) = hh;
                        *(bf162*)(basep + (pnl << 14) + off_lo(r, kk)) = ll;
                    }
                }
            }
        }
    } else {
        #pragma unroll
        for (int mi = 0; mi < 4; mi++) {
            #pragma unroll
            for (int ni = 0; ni < 4; ni++) {
                const int col = bn + warp_n * 32 + ni * 8 + ecol;
                #pragma unroll
                for (int h = 0; h < 2; h++) {
                    const int row = bm + warp_m * 64 + mi * 16 + erow + h * 8;
                    float2 v;
                    v.x = acc[mi][ni][2 * h + 0] * alpha;
                    v.y = acc[mi][ni][2 * h + 1] * alpha;
                    *(float2*)(Cf + zc + (long)row * N + col) = v;
                }
            }
        }
    }

    if (MODE == MODE_SCORES) {
        __syncthreads();                             // smem reuse after loop
        float* red_m = (float*)dynsmem;              // [2][128]
        float* red_s = (float*)(dynsmem + 1024);     // [2][128]

        float lm[4][2];
        #pragma unroll
        for (int ni = 0; ni < 4; ni++)
            #pragma unroll
            for (int cc = 0; cc < 2; cc++) {
                float m = -INFINITY;
                #pragma unroll
                for (int mi = 0; mi < 4; mi++)
                    #pragma unroll
                    for (int h = 0; h < 2; h++)
                        m = fmaxf(m, acc[mi][ni][2 * h + cc] * alpha);
                lm[ni][cc] = m;
            }
        #pragma unroll
        for (int off = 4; off < 32; off <<= 1)
            #pragma unroll
            for (int ni = 0; ni < 4; ni++)
                #pragma unroll
                for (int cc = 0; cc < 2; cc++)
                    lm[ni][cc] = fmaxf(lm[ni][cc],
                        __shfl_xor_sync(0xffffffffu, lm[ni][cc], off));
        if (lane < 4) {
            #pragma unroll
            for (int ni = 0; ni < 4; ni++)
                #pragma unroll
                for (int cc = 0; cc < 2; cc++)
                    red_m[warp_m * 128 + warp_n * 32 + ni * 8 + 2 * lane + cc] = lm[ni][cc];
        }
        __syncthreads();

        float cmax[4][2], lsum[4][2];
        #pragma unroll
        for (int ni = 0; ni < 4; ni++)
            #pragma unroll
            for (int cc = 0; cc < 2; cc++) {
                const int cl = warp_n * 32 + ni * 8 + ecol + cc;
                cmax[ni][cc] = fmaxf(red_m[cl], red_m[128 + cl]);
                float s = 0.f;
                #pragma unroll
                for (int mi = 0; mi < 4; mi++)
                    #pragma unroll
                    for (int h = 0; h < 2; h++)
                        s += __expf(acc[mi][ni][2 * h + cc] * alpha - cmax[ni][cc]);
                lsum[ni][cc] = s;
            }
        #pragma unroll
        for (int off = 4; off < 32; off <<= 1)
            #pragma unroll
            for (int ni = 0; ni < 4; ni++)
                #pragma unroll
                for (int cc = 0; cc < 2; cc++)
                    lsum[ni][cc] += __shfl_xor_sync(0xffffffffu, lsum[ni][cc], off);
        if (lane < 4) {
            #pragma unroll
            for (int ni = 0; ni < 4; ni++)
                #pragma unroll
                for (int cc = 0; cc < 2; cc++)
                    red_s[warp_m * 128 + warp_n * 32 + ni * 8 + 2 * lane + cc] = lsum[ni][cc];
        }
        __syncthreads();

        if (warp_m == 0 && lane < 4) {
            const long pbase = ((long)blockIdx.z * ICH + blockIdx.y) * SEQ + bn;
            #pragma unroll
            for (int ni = 0; ni < 4; ni++)
                #pragma unroll
                for (int cc = 0; cc < 2; cc++) {
                    const int cl = warp_n * 32 + ni * 8 + 2 * lane + cc;
                    pm[pbase + cl] = cmax[ni][cc];
                    ps[pbase + cl] = red_s[cl] + red_s[128 + cl];
                }
        }
    }
}

// ---------------------------------------------------------------------------
// x fp32 -> split panels (4 elems per thread, same 16B chunk)
// ---------------------------------------------------------------------------
__global__ void split_x(const float* __restrict__ src, bf16* __restrict__ dst)
{
    const long i = (long)blockIdx.x * blockDim.x + threadIdx.x;
    const long e4 = i * 4;
    const int row = (int)(e4 >> 9);
    const int k = (int)(e4 & 511);
    float4 a = ((const float4*)src)[i];
    bf162 h0 = __floats2bfloat162_rn(a.x, a.y);
    bf162 h1 = __floats2bfloat162_rn(a.z, a.w);
    float2 f0 = __bfloat1622float2(h0);
    float2 f1 = __bfloat1622float2(h1);
    bf162 l0 = __floats2bfloat162_rn(a.x - f0.x, a.y - f0.y);
    bf162 l1 = __floats2bfloat162_rn(a.z - f1.x, a.w - f1.y);
    const long pnl = (long)(row >> 7) * 16 + (k >> 5);
    const int r = row & 127, kk = k & 31;
    char* base = (char*)dst + (pnl << 14);
    union { bf162 v[2]; uint2 u; } uh, ul;
    uh.v[0] = h0; uh.v[1] = h1;
    ul.v[0] = l0; ul.v[1] = l1;
    *(uint2*)(base + off_hi(r, kk)) = uh.u;
    *(uint2*)(base + off_lo(r, kk)) = ul.u;
}

// ---------------------------------------------------------------------------
// W fp32 [K][N] -> Wt split panels [n][k]; grid.z selects W
// ---------------------------------------------------------------------------
__global__ void transpose_split_w(const float* __restrict__ W0,
                                  const float* __restrict__ W1,
                                  const float* __restrict__ W2,
                                  bf16* __restrict__ T)
{
    __shared__ float tile[32][33];
    const int w = blockIdx.z;
    const float* W = (w == 0) ? W0 : (w == 1) ? W1 : W2;
    const int k0 = blockIdx.y * 32, n0 = blockIdx.x * 32;
    const int tx = threadIdx.x, ty = threadIdx.y;
    #pragma unroll
    for (int yy = 0; yy < 32; yy += 8)
        tile[ty + yy][tx] = W[(long)(k0 + ty + yy) * DMODEL + n0 + tx];
    __syncthreads();
    #pragma unroll
    for (int yy = 0; yy < 32; yy += 8) {
        float v = tile[tx][ty + yy];
        bf16 h = __float2bfloat16_rn(v);
        bf16 l = __float2bfloat16_rn(v - __bfloat162float(h));
        const int ng = w * DMODEL + n0 + ty + yy;
        const int k = k0 + tx;
        const long pnl = (long)(ng >> 7) * 16 + (k >> 5);
        char* base = (char*)T + (pnl << 14);
        *(bf16*)(base + off_hi(ng & 127, k & 31)) = h;
        *(bf16*)(base + off_lo(ng & 127, k & 31)) = l;
    }
}

// ---------------------------------------------------------------------------
// Linear split V -> Vt panels [b][e rows][j], KC=64
// ---------------------------------------------------------------------------
__global__ void transpose_v(const bf16* __restrict__ Vhi, const bf16* __restrict__ Vlo,
                            bf16* __restrict__ Vt)
{
    __shared__ bf16 th[32][33], tl[32][33];
    const long b = blockIdx.z;
    const int e0 = blockIdx.x * 32, n0 = blockIdx.y * 32;
    const int tx = threadIdx.x, ty = threadIdx.y;
    #pragma unroll
    for (int yy = 0; yy < 32; yy += 8) {
        const long src = (b * SEQ + n0 + ty + yy) * DMODEL + e0 + tx;
        th[ty + yy][tx] = Vhi[src];
        tl[ty + yy][tx] = Vlo[src];
    }
    __syncthreads();
    char* bbase = (char*)Vt + b * ((long)DMODEL * SEQ * 4);
    #pragma unroll
    for (int yy = 0; yy < 32; yy += 8) {
        const int e = e0 + ty + yy;
        const int j = n0 + tx;
        const long pnl = (long)(e >> 7) * 64 + (j >> 5);
        char* base = bbase + (pnl << 14);
        *(bf16*)(base + off_hi(e & 127, j & 31)) = th[tx][ty + yy];
        *(bf16*)(base + off_lo(e & 127, j & 31)) = tl[tx][ty + yy];
    }
}

// ---------------------------------------------------------------------------
// Softmax combine + normalize; pass3 writes fp32 output AND W panels (KC=64)
// ---------------------------------------------------------------------------
__global__ void sm_pass2(const float* __restrict__ pm, const float* __restrict__ ps,
                         float* __restrict__ gm, float* __restrict__ gi)
{
    const int j = blockIdx.x * blockDim.x + threadIdx.x;
    const long b = blockIdx.y;
    float m = -INFINITY;
    #pragma unroll
    for (int ic = 0; ic < ICH; ic++)
        m = fmaxf(m, pm[(b * ICH + ic) * SEQ + j]);
    float s = 0.0f;
    #pragma unroll
    for (int ic = 0; ic < ICH; ic++)
        s += ps[(b * ICH + ic) * SEQ + j] * __expf(pm[(b * ICH + ic) * SEQ + j] - m);
    gm[b * SEQ + j] = m;
    gi[b * SEQ + j] = 1.0f / s;
}

__global__ void sm_pass3(float* __restrict__ S,
                         const float* __restrict__ gm, const float* __restrict__ gi,
                         bf16* __restrict__ Wp)
{
    const int j4 = (blockIdx.x * blockDim.x + threadIdx.x) * 4;
    const int i = blockIdx.y;
    const long b = blockIdx.z;
    const long off = b * (long)SEQ * SEQ + (long)i * SEQ + j4;
    float4 x = *(const float4*)(S + off);
    float4 m = *(const float4*)(gm + b * SEQ + j4);
    float4 v = *(const float4*)(gi + b * SEQ + j4);
    float4 w;
    w.x = __expf(x.x - m.x) * v.x;
    w.y = __expf(x.y - m.y) * v.y;
    w.z = __expf(x.z - m.z) * v.z;
    w.w = __expf(x.w - m.w) * v.w;
    *(float4*)(S + off) = w;
    bf162 h0 = __floats2bfloat162_rn(w.x, w.y);
    bf162 h1 = __floats2bfloat162_rn(w.z, w.w);
    float2 f0 = __bfloat1622float2(h0);
    float2 f1 = __bfloat1622float2(h1);
    bf162 l0 = __floats2bfloat162_rn(w.x - f0.x, w.y - f0.y);
    bf162 l1 = __floats2bfloat162_rn(w.z - f1.x, w.w - f1.y);
    char* bbase = (char*)Wp + b * ((long)SEQ * SEQ * 4);
    const long pnl = (long)(i >> 7) * 64 + (j4 >> 5);
    char* base = bbase + (pnl << 14);
    const int r = i & 127, kk = j4 & 31;
    union { bf162 v[2]; uint2 u; } uh, ul;
    uh.v[0] = h0; uh.v[1] = h1;
    ul.v[0] = l0; ul.v[1] = l1;
    *(uint2*)(base + off_hi(r, kk)) = uh.u;
    *(uint2*)(base + off_lo(r, kk)) = ul.u;
}

// ---------------------------------------------------------------------------
// kernel_launch — two-stream per-half pipeline to fill wave-quantization tails
// ---------------------------------------------------------------------------
extern "C" void kernel_launch(void* const* d_in, const int* in_sizes, int n_in,
                              void* d_out, int out_size)
{
    const float* x  = (const float*)d_in[0];
    const float* Wq = (const float*)d_in[1];
    const float* bq = (const float*)d_in[2];
    const float* Wk = (const float*)d_in[3];
    const float* bk = (const float*)d_in[4];
    const float* Wv = (const float*)d_in[5];
    const float* bv = (const float*)d_in[6];

    float* out     = (float*)d_out;
    float* weights = out + (long)BATCH * SEQ * DMODEL;

    bf16 *xp, *Wtp, *Qp, *Kp, *Vhi, *Vlo, *Vtp, *Wp;
    float *pm, *ps, *gm, *gi;
    cudaGetSymbolAddress((void**)&xp, g_x);
    cudaGetSymbolAddress((void**)&Wtp, g_Wt);
    cudaGetSymbolAddress((void**)&Qp, g_Q);
    cudaGetSymbolAddress((void**)&Kp, g_K);
    cudaGetSymbolAddress((void**)&Vhi, g_Vhi);
    cudaGetSymbolAddress((void**)&Vlo, g_Vlo);
    cudaGetSymbolAddress((void**)&Vtp, g_Vt);
    cudaGetSymbolAddress((void**)&Wp, g_W);
    cudaGetSymbolAddress((void**)&pm, g_pm);
    cudaGetSymbolAddress((void**)&ps, g_ps);
    cudaGetSymbolAddress((void**)&gm, g_gm);
    cudaGetSymbolAddress((void**)&gi, g_gi);

    static bool init_done = false;
    static cudaStream_t s1, s2;
    static cudaEvent_t evF, evW, evP, evV, evS1;
    if (!init_done) {
        cudaFuncSetAttribute(gemm_ps<MODE_PROJ>,
                             cudaFuncAttributeMaxDynamicSharedMemorySize, DYN_SMEM);
        cudaFuncSetAttribute(gemm_ps<MODE_SCORES>,
                             cudaFuncAttributeMaxDynamicSharedMemorySize, DYN_SMEM);
        cudaFuncSetAttribute(gemm_ps<MODE_AV>,
                             cudaFuncAttributeMaxDynamicSharedMemorySize, DYN_SMEM);
        cudaStreamCreateWithFlags(&s1, cudaStreamNonBlocking);
        cudaStreamCreateWithFlags(&s2, cudaStreamNonBlocking);
        cudaEventCreateWithFlags(&evF, cudaEventDisableTiming);
        cudaEventCreateWithFlags(&evW, cudaEventDisableTiming);
        cudaEventCreateWithFlags(&evP, cudaEventDisableTiming);
        cudaEventCreateWithFlags(&evV, cudaEventDisableTiming);
        cudaEventCreateWithFlags(&evS1, cudaEventDisableTiming);
        init_done = true;
    }

    const dim3 blk(256);
    const float scale = 1.0f / sqrtf((float)DMODEL);
    const int HB = BATCH / 2;   // 4 batches per half

    // Per-half pointer offsets (half h covers batches [4h, 4h+4))
    const long oQK = (long)HB * SEQ * DMODEL * 2;       // bf16 elems
    const long oW  = (long)HB * SEQ * SEQ;              // fp32 elems
    const long oWp = (long)HB * SEQ * SEQ * 2;          // bf16 elems
    const long oVt = (long)HB * DMODEL * SEQ * 2;       // bf16 elems
    const long oPm = (long)HB * ICH * SEQ;
    const long oG  = (long)HB * SEQ;
    const long oOut = (long)HB * SEQ * DMODEL;

    // ---- Fork: s2 runs W transpose concurrent with split_x ----
    cudaEventRecord(evF, 0);
    cudaStreamWaitEvent(s2, evF, 0);
    split_x<<<(BATCH * SEQ * DMODEL / 4) / 256, blk>>>(x, xp);
    {
        dim3 g(16, 16, 3), b(32, 8);
        transpose_split_w<<<g, b, 0, s2>>>(Wq, Wk, Wv, Wtp);
    }
    cudaEventRecord(evW, s2);
    cudaStreamWaitEvent(0, evW, 0);

    // 1) fused QKV projection (all batches)
    {
        dim3 grid(3 * DMODEL / BN, (BATCH * SEQ) / BM, 1);
        gemm_ps<MODE_PROJ><<<grid, blk, DYN_SMEM>>>(
            (const char*)xp, (const char*)Wtp, 1.0f, 3 * DMODEL, DMODEL / 32,
            0, 0, 0, nullptr, nullptr, nullptr, bq, bk, bv, Qp, Kp, Vhi, Vlo);
    }
    cudaEventRecord(evP, 0);

    // transpose_v on s2 (all batches), concurrent with scores
    cudaStreamWaitEvent(s2, evP, 0);
    {
        dim3 g(DMODEL / 32, SEQ / 32, BATCH), b(32, 8);
        transpose_v<<<g, b, 0, s2>>>(Vhi, Vlo, Vtp);
    }
    cudaEventRecord(evV, s2);

    // s1 handles half 1 (batches 4-7)
    cudaStreamWaitEvent(s1, evP, 0);

    dim3 gridS(SEQ / BN, SEQ / BM, HB);
    dim3 gridAV(DMODEL / BN, SEQ / BM, HB);
    dim3 g2(SEQ / 256, HB);
    dim3 g3(SEQ / (256 * 4), SEQ, HB);

    // ---- Half 0 on default stream ----
    gemm_ps<MODE_SCORES><<<gridS, blk, DYN_SMEM>>>(
        (const char*)Qp, (const char*)Kp, scale, SEQ, DMODEL / 32,
        (long)SEQ * DMODEL * 4, (long)SEQ * DMODEL * 4, (long)SEQ * SEQ,
        weights, pm, ps, nullptr, nullptr, nullptr,
        nullptr, nullptr, nullptr, nullptr);
    sm_pass2<<<g2, blk>>>(pm, ps, gm, gi);
    sm_pass3<<<g3, blk>>>(weights, gm, gi, Wp);
    cudaStreamWaitEvent(0, evV, 0);
    gemm_ps<MODE_AV><<<gridAV, blk, DYN_SMEM>>>(
        (const char*)Wp, (const char*)Vtp, 1.0f, DMODEL, SEQ / 32,
        (long)SEQ * SEQ * 4, (long)DMODEL * SEQ * 4, (long)SEQ * DMODEL,
        out, nullptr, nullptr, nullptr, nullptr, nullptr,
        nullptr, nullptr, nullptr, nullptr);

    // ---- Half 1 on s1 ----
    gemm_ps<MODE_SCORES><<<gridS, blk, DYN_SMEM, s1>>>(
        (const char*)(Qp + oQK), (const char*)(Kp + oQK), scale, SEQ, DMODEL / 32,
        (long)SEQ * DMODEL * 4, (long)SEQ * DMODEL * 4, (long)SEQ * SEQ,
        weights + oW, pm + oPm, ps + oPm, nullptr, nullptr, nullptr,
        nullptr, nullptr, nullptr, nullptr);
    sm_pass2<<<g2, blk, 0, s1>>>(pm + oPm, ps + oPm, gm + oG, gi + oG);
    sm_pass3<<<g3, blk, 0, s1>>>(weights + oW, gm + oG, gi + oG, Wp + oWp);
    cudaStreamWaitEvent(s1, evV, 0);
    gemm_ps<MODE_AV><<<gridAV, blk, DYN_SMEM, s1>>>(
        (const char*)(Wp + oWp), (const char*)(Vtp + oVt), 1.0f, DMODEL, SEQ / 32,
        (long)SEQ * SEQ * 4, (long)DMODEL * SEQ * 4, (long)SEQ * DMODEL,
        out + oOut, nullptr, nullptr, nullptr, nullptr, nullptr,
        nullptr, nullptr, nullptr, nullptr);

    // ---- Join ----
    cudaEventRecord(evS1, s1);
    cudaStreamWaitEvent(0, evS1, 0);
}

// round 17
// speedup vs baseline: 1.2635x; 1.0281x over previous
#include <cuda_runtime.h>
#include <cuda_bf16.h>
#include <math.h>
#include <stdint.h>

// Problem constants
#define BATCH 8
#define SEQ   2048
#define DMODEL 512

#define BM 128
#define BN 128
// tile: 128 rows x 128B (hi bytes [0,64), lo [64,128)), XOR-swizzled, = 16KB
#define TILE_B  16384
#define STAGE_B (2 * TILE_B)
#define NSTAGE  3
#define DYN_SMEM (NSTAGE * STAGE_B)   // 96 KB

#define ICH 16
#define MODE_PROJ   0
#define MODE_SCORES 1
#define MODE_AV     2

typedef __nv_bfloat16 bf16;
typedef __nv_bfloat162 bf162;

// ---------------------------------------------------------------------------
// Device scratch: panel (tile-major, pre-swizzled) arrays hold hi+lo combined.
// ---------------------------------------------------------------------------
__device__ bf16 g_x[(long)BATCH * SEQ * DMODEL * 2];        // panels, KC=16
__device__ bf16 g_Wt[3L * DMODEL * DMODEL * 2];             // panels, KC=16
__device__ bf16 g_Q[(long)BATCH * SEQ * DMODEL * 2];        // panels, KC=16
__device__ bf16 g_K[(long)BATCH * SEQ * DMODEL * 2];        // panels, KC=16
__device__ bf16 g_Vhi[(long)BATCH * SEQ * DMODEL];          // linear
__device__ bf16 g_Vlo[(long)BATCH * SEQ * DMODEL];          // linear
__device__ bf16 g_Vt[(long)BATCH * DMODEL * SEQ * 2];       // panels, KC=64
__device__ bf16 g_W[(long)BATCH * SEQ * SEQ * 2];           // panels, KC=64
__device__ float g_pm[BATCH * ICH * SEQ], g_ps[BATCH * ICH * SEQ];
__device__ float g_gm[BATCH * SEQ], g_gi[BATCH * SEQ];

// Panel element addressing (within a 16KB tile)
__device__ __forceinline__ uint32_t off_hi(int r, int kk) {
    return (uint32_t)((r << 7) + ((((kk >> 3) << 4) ^ ((r & 7) << 4)) | ((kk & 7) << 1)));
}
__device__ __forceinline__ uint32_t off_lo(int r, int kk) {
    return (uint32_t)((r << 7) + (((((kk >> 3) + 4) << 4) ^ ((r & 7) << 4)) | ((kk & 7) << 1)));
}

// ---------------------------------------------------------------------------
// PTX helpers
// ---------------------------------------------------------------------------
__device__ __forceinline__ uint32_t smem_u32(const void* p) {
    uint32_t a;
    asm("{ .reg .u64 t; cvta.to.shared.u64 t, %1; cvt.u32.u64 %0, t; }"
        : "=r"(a) : "l"(p));
    return a;
}
__device__ __forceinline__ void ldm_x4(uint32_t* r, uint32_t addr) {
    asm volatile("ldmatrix.sync.aligned.m8n8.x4.shared.b16 {%0,%1,%2,%3}, [%4];"
        : "=r"(r[0]), "=r"(r[1]), "=r"(r[2]), "=r"(r[3]) : "r"(addr));
}
__device__ __forceinline__ void mma16816(float* c, const uint32_t* a, const uint32_t* b) {
    asm volatile(
        "mma.sync.aligned.m16n8k16.row.col.f32.bf16.bf16.f32 "
        "{%0,%1,%2,%3}, {%4,%5,%6,%7}, {%8,%9}, {%0,%1,%2,%3};"
        : "+f"(c[0]), "+f"(c[1]), "+f"(c[2]), "+f"(c[3])
        : "r"(a[0]), "r"(a[1]), "r"(a[2]), "r"(a[3]), "r"(b[0]), "r"(b[1]));
}

#define MBARRIER_INIT(addr, cnt) \
    asm volatile("mbarrier.init.shared.b64 [%0], %1;" \
                 :: "r"((uint32_t)(addr)), "r"((uint32_t)(cnt)) : "memory")
#define MBARRIER_EXPECT_TX(addr, bytes) \
    asm volatile("mbarrier.arrive.expect_tx.shared.b64 _, [%0], %1;" \
                 :: "r"((uint32_t)(addr)), "r"((uint32_t)(bytes)) : "memory")
#define MBARRIER_ARRIVE(addr) \
    asm volatile("mbarrier.arrive.shared.b64 _, [%0];" \
                 :: "r"((uint32_t)(addr)) : "memory")
#define CP_BULK(dst, src, bytes, bar) \
    asm volatile("cp.async.bulk.shared::cta.global.mbarrier::complete_tx::bytes " \
                 "[%0], [%1], %2, [%3];" \
                 :: "r"((uint32_t)(dst)), "l"(src), "r"((uint32_t)(bytes)), \
                    "r"((uint32_t)(bar)) : "memory")
#define FENCE_PROXY_ASYNC() \
    asm volatile("fence.proxy.async.shared::cta;" ::: "memory")

#define MBARRIER_WAIT_PARITY(mbar_smem_addr, phase_parity) do { \
    uint32_t _mbar = (uint32_t)(mbar_smem_addr); \
    uint32_t _parity = (uint32_t)(phase_parity); \
    uint32_t _done; \
    asm volatile( \
        "{\n\t.reg .pred p;\n\t" \
        "mbarrier.try_wait.parity.acquire.cta.shared::cta.b64 p, [%1], %2;\n\t" \
        "selp.b32 %0, 1, 0, p;\n\t}" \
        : "=r"(_done) : "r"(_mbar), "r"(_parity) : "memory"); \
    if (!_done) { \
        asm volatile( \
            "{\n\t.reg .pred P1;\n\t" \
            "WAIT_LOOP_%=:\n\t" \
            "mbarrier.try_wait.parity.acquire.cta.shared::cta.b64 P1, [%0], %1, 0x989680;\n\t" \
            "@P1 bra.uni WAIT_DONE_%=;\n\t" \
            "bra.uni WAIT_LOOP_%=;\n\t" \
            "WAIT_DONE_%=:\n\t}" \
            :: "r"(_mbar), "r"(_parity) : "memory"); \
    } \
} while(0)

// ===========================================================================
// GEMM on panel-layout split bf16, 3-term split (hh+hl+lh).
// Tiles fetched with cp.async.bulk (16KB each) into a 3-stage smem ring with
// full/empty mbarriers (no per-chunk __syncthreads).
// CTA tile 128x128, 256 threads (2 warp_m x 4 warp_n, 64x32 warp tiles).
// ===========================================================================
template<int MODE>
__global__ __launch_bounds__(256, 2)
void gemm_ps(const char* __restrict__ Ab, const char* __restrict__ Bb,
             float alpha, int N, int KC, long sA, long sB, long sC,
             float* __restrict__ Cf,
             float* __restrict__ pm, float* __restrict__ ps,
             const float* __restrict__ bq, const float* __restrict__ bk,
             const float* __restrict__ bv,
             bf16* __restrict__ Qp, bf16* __restrict__ Kp,
             bf16* __restrict__ Vhi, bf16* __restrict__ Vlo)
{
    const char* A = Ab + (long)blockIdx.z * sA;
    const char* B = Bb + (long)blockIdx.z * sB;
    const long zc = (long)blockIdx.z * sC;
    const int bm = blockIdx.y * BM;
    const int bn = blockIdx.x * BN;
    const int tid = threadIdx.x;
    const int wid = tid >> 5, lane = tid & 31;
    const int warp_m = wid & 1;
    const int warp_n = wid >> 1;

    extern __shared__ __align__(16) char dynsmem[];
    const uint32_t sbase = smem_u32(dynsmem);
    __shared__ __align__(8) unsigned long long s_bar[NSTAGE];
    __shared__ __align__(8) unsigned long long s_emp[NSTAGE];
    const uint32_t bar0 = smem_u32(s_bar);
    const uint32_t emp0 = smem_u32(s_emp);

    if (tid == 0) {
        #pragma unroll
        for (int s = 0; s < NSTAGE; s++) {
            MBARRIER_INIT(bar0 + s * 8, 1);
            MBARRIER_INIT(emp0 + s * 8, 256);
        }
        FENCE_PROXY_ASYNC();
    }
    __syncthreads();

    float acc[4][4][4] = {};

    const int a_row = warp_m * 64 + (lane & 15);
    const uint32_t a_k = (uint32_t)(((lane >> 4) * 8) * 2);
    const int b_row = warp_n * 32 + (lane & 7) + ((lane >> 4) * 8);
    const uint32_t b_k = (uint32_t)((((lane >> 3) & 1) * 8) * 2);
    const uint32_t swz = (uint32_t)((lane & 7) << 4);

    const int nch = KC;
    const long pA = (long)blockIdx.y * KC;   // A panel row-block
    const long pB = (long)blockIdx.x * KC;

    // Prologue: issue chunks 0 and 1 (chunk 2 issued at c=0 in the loop)
    if (tid == 0) {
        #pragma unroll
        for (int c = 0; c < 2; c++) {
            const uint32_t bar = bar0 + c * 8;
            MBARRIER_EXPECT_TX(bar, 2 * TILE_B);
            CP_BULK(sbase + c * STAGE_B,          A + ((pA + c) << 14), TILE_B, bar);
            CP_BULK(sbase + c * STAGE_B + TILE_B, B + ((pB + c) << 14), TILE_B, bar);
        }
    }

    for (int c = 0; c < nch; c++) {
        // Producer: issue chunk c+2 into stage (c+2)%3 once its previous
        // consumers have all arrived on the stage's empty barrier.
        if (tid == 0 && c + 2 < nch) {
            const int s = (c + 2) % NSTAGE;
            if (c + 2 >= NSTAGE)
                MBARRIER_WAIT_PARITY(emp0 + s * 8, (((c + 2) / NSTAGE) - 1) & 1);
            const uint32_t bar = bar0 + s * 8;
            MBARRIER_EXPECT_TX(bar, 2 * TILE_B);
            CP_BULK(sbase + s * STAGE_B,          A + ((pA + c + 2) << 14), TILE_B, bar);
            CP_BULK(sbase + s * STAGE_B + TILE_B, B + ((pB + c + 2) << 14), TILE_B, bar);
        }

        const int st = c % NSTAGE;
        MBARRIER_WAIT_PARITY(bar0 + st * 8, (c / NSTAGE) & 1);

        const uint32_t uA = sbase + st * STAGE_B;
        const uint32_t uB = uA + TILE_B;

        #pragma unroll
        for (int ks = 0; ks < 2; ks++) {
            const uint32_t akh = ((a_k + ks * 32) ^ swz);
            const uint32_t akl = ((a_k + ks * 32 + 64) ^ swz);
            const uint32_t bkh = ((b_k + ks * 32) ^ swz);
            const uint32_t bkl = ((b_k + ks * 32 + 64) ^ swz);
            uint32_t afh[4][4], afl[4][4], bfh[2][4], bfl[2][4];
            // Load afh, bfh, bfl up front -> LDSM latency hides under hh MMAs
            #pragma unroll
            for (int mi = 0; mi < 4; mi++)
                ldm_x4(afh[mi], uA + (uint32_t)((a_row + mi * 16) * 128) + akh);
            #pragma unroll
            for (int nb2 = 0; nb2 < 2; nb2++)
                ldm_x4(bfh[nb2], uB + (uint32_t)((b_row + nb2 * 16) * 128) + bkh);
            #pragma unroll
            for (int nb2 = 0; nb2 < 2; nb2++)
                ldm_x4(bfl[nb2], uB + (uint32_t)((b_row + nb2 * 16) * 128) + bkl);
            #pragma unroll
            for (int mi = 0; mi < 4; mi++)
                #pragma unroll
                for (int ni = 0; ni < 4; ni++)
                    mma16816(acc[mi][ni], afh[mi], &bfh[ni >> 1][(ni & 1) * 2]);
            #pragma unroll
            for (int mi = 0; mi < 4; mi++)
                ldm_x4(afl[mi], uA + (uint32_t)((a_row + mi * 16) * 128) + akl);
            #pragma unroll
            for (int mi = 0; mi < 4; mi++)
                #pragma unroll
                for (int ni = 0; ni < 4; ni++)
                    mma16816(acc[mi][ni], afh[mi], &bfl[ni >> 1][(ni & 1) * 2]);
            #pragma unroll
            for (int mi = 0; mi < 4; mi++)
                #pragma unroll
                for (int ni = 0; ni < 4; ni++)
                    mma16816(acc[mi][ni], afl[mi], &bfh[ni >> 1][(ni & 1) * 2]);
        }
        // All smem reads for this chunk done (LDSM is synchronous) -> release
        MBARRIER_ARRIVE(emp0 + st * 8);
    }

    // ---------------- Epilogue ----------------
    const int erow = lane >> 2;
    const int ecol = 2 * (lane & 3);

    if (MODE == MODE_PROJ) {
        #pragma unroll
        for (int mi = 0; mi < 4; mi++) {
            #pragma unroll
            for (int ni = 0; ni < 4; ni++) {
                const int col = bn + warp_n * 32 + ni * 8 + ecol;
                const int sel = col >> 9;
                const int nn = col & 511;
                const float* bp = (sel == 0) ? bq : (sel == 1) ? bk : bv;
                const float bx = bp[nn], by = bp[nn + 1];
                #pragma unroll
                for (int h = 0; h < 2; h++) {
                    const int row = bm + warp_m * 64 + mi * 16 + erow + h * 8;
                    float vx = acc[mi][ni][2 * h + 0] + bx;
                    float vy = acc[mi][ni][2 * h + 1] + by;
                    bf162 hh = __floats2bfloat162_rn(vx, vy);
                    float2 hf = __bfloat1622float2(hh);
                    bf162 ll = __floats2bfloat162_rn(vx - hf.x, vy - hf.y);
                    if (sel == 2) {
                        const long off = (long)row * DMODEL + nn;
                        *(bf162*)(Vhi + off) = hh;
                        *(bf162*)(Vlo + off) = ll;
                    } else {
                        char* basep = (char*)((sel == 0) ? Qp : Kp);
                        const long pnl = (long)(row >> 7) * 16 + (nn >> 5);
                        const int r = row & 127, kk = nn & 31;
                        *(bf162*)(basep + (pnl << 14) + off_hi(r, kk)) = hh;
                        *(bf162*)(basep + (pnl << 14) + off_lo(r, kk)) = ll;
                    }
                }
            }
        }
    } else {
        #pragma unroll
        for (int mi = 0; mi < 4; mi++) {
            #pragma unroll
            for (int ni = 0; ni < 4; ni++) {
                const int col = bn + warp_n * 32 + ni * 8 + ecol;
                #pragma unroll
                for (int h = 0; h < 2; h++) {
                    const int row = bm + warp_m * 64 + mi * 16 + erow + h * 8;
                    float2 v;
                    v.x = acc[mi][ni][2 * h + 0] * alpha;
                    v.y = acc[mi][ni][2 * h + 1] * alpha;
                    *(float2*)(Cf + zc + (long)row * N + col) = v;
                }
            }
        }
    }

    if (MODE == MODE_SCORES) {
        __syncthreads();                             // smem reuse after loop
        float* red_m = (float*)dynsmem;              // [2][128]
        float* red_s = (float*)(dynsmem + 1024);     // [2][128]

        float lm[4][2];
        #pragma unroll
        for (int ni = 0; ni < 4; ni++)
            #pragma unroll
            for (int cc = 0; cc < 2; cc++) {
                float m = -INFINITY;
                #pragma unroll
                for (int mi = 0; mi < 4; mi++)
                    #pragma unroll
                    for (int h = 0; h < 2; h++)
                        m = fmaxf(m, acc[mi][ni][2 * h + cc] * alpha);
                lm[ni][cc] = m;
            }
        #pragma unroll
        for (int off = 4; off < 32; off <<= 1)
            #pragma unroll
            for (int ni = 0; ni < 4; ni++)
                #pragma unroll
                for (int cc = 0; cc < 2; cc++)
                    lm[ni][cc] = fmaxf(lm[ni][cc],
                        __shfl_xor_sync(0xffffffffu, lm[ni][cc], off));
        if (lane < 4) {
            #pragma unroll
            for (int ni = 0; ni < 4; ni++)
                #pragma unroll
                for (int cc = 0; cc < 2; cc++)
                    red_m[warp_m * 128 + warp_n * 32 + ni * 8 + 2 * lane + cc] = lm[ni][cc];
        }
        __syncthreads();

        float cmax[4][2], lsum[4][2];
        #pragma unroll
        for (int ni = 0; ni < 4; ni++)
            #pragma unroll
            for (int cc = 0; cc < 2; cc++) {
                const int cl = warp_n * 32 + ni * 8 + ecol + cc;
                cmax[ni][cc] = fmaxf(red_m[cl], red_m[128 + cl]);
                float s = 0.f;
                #pragma unroll
                for (int mi = 0; mi < 4; mi++)
                    #pragma unroll
                    for (int h = 0; h < 2; h++)
                        s += __expf(acc[mi][ni][2 * h + cc] * alpha - cmax[ni][cc]);
                lsum[ni][cc] = s;
            }
        #pragma unroll
        for (int off = 4; off < 32; off <<= 1)
            #pragma unroll
            for (int ni = 0; ni < 4; ni++)
                #pragma unroll
                for (int cc = 0; cc < 2; cc++)
                    lsum[ni][cc] += __shfl_xor_sync(0xffffffffu, lsum[ni][cc], off);
        if (lane < 4) {
            #pragma unroll
            for (int ni = 0; ni < 4; ni++)
                #pragma unroll
                for (int cc = 0; cc < 2; cc++)
                    red_s[warp_m * 128 + warp_n * 32 + ni * 8 + 2 * lane + cc] = lsum[ni][cc];
        }
        __syncthreads();

        if (warp_m == 0 && lane < 4) {
            const long pbase = ((long)blockIdx.z * ICH + blockIdx.y) * SEQ + bn;
            #pragma unroll
            for (int ni = 0; ni < 4; ni++)
                #pragma unroll
                for (int cc = 0; cc < 2; cc++) {
                    const int cl = warp_n * 32 + ni * 8 + 2 * lane + cc;
                    pm[pbase + cl] = cmax[ni][cc];
                    ps[pbase + cl] = red_s[cl] + red_s[128 + cl];
                }
        }
    }
}

// ---------------------------------------------------------------------------
// x fp32 -> split panels (4 elems per thread, same 16B chunk)
// ---------------------------------------------------------------------------
__global__ void split_x(const float* __restrict__ src, bf16* __restrict__ dst)
{
    const long i = (long)blockIdx.x * blockDim.x + threadIdx.x;
    const long e4 = i * 4;
    const int row = (int)(e4 >> 9);
    const int k = (int)(e4 & 511);
    float4 a = ((const float4*)src)[i];
    bf162 h0 = __floats2bfloat162_rn(a.x, a.y);
    bf162 h1 = __floats2bfloat162_rn(a.z, a.w);
    float2 f0 = __bfloat1622float2(h0);
    float2 f1 = __bfloat1622float2(h1);
    bf162 l0 = __floats2bfloat162_rn(a.x - f0.x, a.y - f0.y);
    bf162 l1 = __floats2bfloat162_rn(a.z - f1.x, a.w - f1.y);
    const long pnl = (long)(row >> 7) * 16 + (k >> 5);
    const int r = row & 127, kk = k & 31;
    char* base = (char*)dst + (pnl << 14);
    union { bf162 v[2]; uint2 u; } uh, ul;
    uh.v[0] = h0; uh.v[1] = h1;
    ul.v[0] = l0; ul.v[1] = l1;
    *(uint2*)(base + off_hi(r, kk)) = uh.u;
    *(uint2*)(base + off_lo(r, kk)) = ul.u;
}

// ---------------------------------------------------------------------------
// W fp32 [K][N] -> Wt split panels [n][k]; grid.z selects W
// ---------------------------------------------------------------------------
__global__ void transpose_split_w(const float* __restrict__ W0,
                                  const float* __restrict__ W1,
                                  const float* __restrict__ W2,
                                  bf16* __restrict__ T)
{
    __shared__ float tile[32][33];
    const int w = blockIdx.z;
    const float* W = (w == 0) ? W0 : (w == 1) ? W1 : W2;
    const int k0 = blockIdx.y * 32, n0 = blockIdx.x * 32;
    const int tx = threadIdx.x, ty = threadIdx.y;
    #pragma unroll
    for (int yy = 0; yy < 32; yy += 8)
        tile[ty + yy][tx] = W[(long)(k0 + ty + yy) * DMODEL + n0 + tx];
    __syncthreads();
    #pragma unroll
    for (int yy = 0; yy < 32; yy += 8) {
        float v = tile[tx][ty + yy];
        bf16 h = __float2bfloat16_rn(v);
        bf16 l = __float2bfloat16_rn(v - __bfloat162float(h));
        const int ng = w * DMODEL + n0 + ty + yy;
        const int k = k0 + tx;
        const long pnl = (long)(ng >> 7) * 16 + (k >> 5);
        char* base = (char*)T + (pnl << 14);
        *(bf16*)(base + off_hi(ng & 127, k & 31)) = h;
        *(bf16*)(base + off_lo(ng & 127, k & 31)) = l;
    }
}

// ---------------------------------------------------------------------------
// Linear split V -> Vt panels [b][e rows][j], KC=64
// ---------------------------------------------------------------------------
__global__ void transpose_v(const bf16* __restrict__ Vhi, const bf16* __restrict__ Vlo,
                            bf16* __restrict__ Vt)
{
    __shared__ bf16 th[32][33], tl[32][33];
    const long b = blockIdx.z;
    const int e0 = blockIdx.x * 32, n0 = blockIdx.y * 32;
    const int tx = threadIdx.x, ty = threadIdx.y;
    #pragma unroll
    for (int yy = 0; yy < 32; yy += 8) {
        const long src = (b * SEQ + n0 + ty + yy) * DMODEL + e0 + tx;
        th[ty + yy][tx] = Vhi[src];
        tl[ty + yy][tx] = Vlo[src];
    }
    __syncthreads();
    char* bbase = (char*)Vt + b * ((long)DMODEL * SEQ * 4);
    #pragma unroll
    for (int yy = 0; yy < 32; yy += 8) {
        const int e = e0 + ty + yy;
        const int j = n0 + tx;
        const long pnl = (long)(e >> 7) * 64 + (j >> 5);
        char* base = bbase + (pnl << 14);
        *(bf16*)(base + off_hi(e & 127, j & 31)) = th[tx][ty + yy];
        *(bf16*)(base + off_lo(e & 127, j & 31)) = tl[tx][ty + yy];
    }
}

// ---------------------------------------------------------------------------
// Softmax combine + normalize; pass3 writes fp32 output AND W panels (KC=64)
// ---------------------------------------------------------------------------
__global__ void sm_pass2(const float* __restrict__ pm, const float* __restrict__ ps,
                         float* __restrict__ gm, float* __restrict__ gi)
{
    const int j = blockIdx.x * blockDim.x + threadIdx.x;
    const long b = blockIdx.y;
    float m = -INFINITY;
    #pragma unroll
    for (int ic = 0; ic < ICH; ic++)
        m = fmaxf(m, pm[(b * ICH + ic) * SEQ + j]);
    float s = 0.0f;
    #pragma unroll
    for (int ic = 0; ic < ICH; ic++)
        s += ps[(b * ICH + ic) * SEQ + j] * __expf(pm[(b * ICH + ic) * SEQ + j] - m);
    gm[b * SEQ + j] = m;
    gi[b * SEQ + j] = 1.0f / s;
}

__global__ void sm_pass3(float* __restrict__ S,
                         const float* __restrict__ gm, const float* __restrict__ gi,
                         bf16* __restrict__ Wp)
{
    const int j4 = (blockIdx.x * blockDim.x + threadIdx.x) * 4;
    const int i = blockIdx.y;
    const long b = blockIdx.z;
    const long off = b * (long)SEQ * SEQ + (long)i * SEQ + j4;
    float4 x = *(const float4*)(S + off);
    float4 m = *(const float4*)(gm + b * SEQ + j4);
    float4 v = *(const float4*)(gi + b * SEQ + j4);
    float4 w;
    w.x = __expf(x.x - m.x) * v.x;
    w.y = __expf(x.y - m.y) * v.y;
    w.z = __expf(x.z - m.z) * v.z;
    w.w = __expf(x.w - m.w) * v.w;
    *(float4*)(S + off) = w;
    bf162 h0 = __floats2bfloat162_rn(w.x, w.y);
    bf162 h1 = __floats2bfloat162_rn(w.z, w.w);
    float2 f0 = __bfloat1622float2(h0);
    float2 f1 = __bfloat1622float2(h1);
    bf162 l0 = __floats2bfloat162_rn(w.x - f0.x, w.y - f0.y);
    bf162 l1 = __floats2bfloat162_rn(w.z - f1.x, w.w - f1.y);
    char* bbase = (char*)Wp + b * ((long)SEQ * SEQ * 4);
    const long pnl = (long)(i >> 7) * 64 + (j4 >> 5);
    char* base = bbase + (pnl << 14);
    const int r = i & 127, kk = j4 & 31;
    union { bf162 v[2]; uint2 u; } uh, ul;
    uh.v[0] = h0; uh.v[1] = h1;
    ul.v[0] = l0; ul.v[1] = l1;
    *(uint2*)(base + off_hi(r, kk)) = uh.u;
    *(uint2*)(base + off_lo(r, kk)) = ul.u;
}

// ---------------------------------------------------------------------------
// kernel_launch — per-half end-to-end pipeline (proj through AV) on 2 streams
// ---------------------------------------------------------------------------
extern "C" void kernel_launch(void* const* d_in, const int* in_sizes, int n_in,
                              void* d_out, int out_size)
{
    const float* x  = (const float*)d_in[0];
    const float* Wq = (const float*)d_in[1];
    const float* bq = (const float*)d_in[2];
    const float* Wk = (const float*)d_in[3];
    const float* bk = (const float*)d_in[4];
    const float* Wv = (const float*)d_in[5];
    const float* bv = (const float*)d_in[6];

    float* out     = (float*)d_out;
    float* weights = out + (long)BATCH * SEQ * DMODEL;

    bf16 *xp, *Wtp, *Qp, *Kp, *Vhi, *Vlo, *Vtp, *Wp;
    float *pm, *ps, *gm, *gi;
    cudaGetSymbolAddress((void**)&xp, g_x);
    cudaGetSymbolAddress((void**)&Wtp, g_Wt);
    cudaGetSymbolAddress((void**)&Qp, g_Q);
    cudaGetSymbolAddress((void**)&Kp, g_K);
    cudaGetSymbolAddress((void**)&Vhi, g_Vhi);
    cudaGetSymbolAddress((void**)&Vlo, g_Vlo);
    cudaGetSymbolAddress((void**)&Vtp, g_Vt);
    cudaGetSymbolAddress((void**)&Wp, g_W);
    cudaGetSymbolAddress((void**)&pm, g_pm);
    cudaGetSymbolAddress((void**)&ps, g_ps);
    cudaGetSymbolAddress((void**)&gm, g_gm);
    cudaGetSymbolAddress((void**)&gi, g_gi);

    static bool init_done = false;
    static cudaStream_t s1, s2;
    static cudaEvent_t evF, evW, evX, evP0, evP1, evV0, evV1, evS1;
    if (!init_done) {
        cudaFuncSetAttribute(gemm_ps<MODE_PROJ>,
                             cudaFuncAttributeMaxDynamicSharedMemorySize, DYN_SMEM);
        cudaFuncSetAttribute(gemm_ps<MODE_SCORES>,
                             cudaFuncAttributeMaxDynamicSharedMemorySize, DYN_SMEM);
        cudaFuncSetAttribute(gemm_ps<MODE_AV>,
                             cudaFuncAttributeMaxDynamicSharedMemorySize, DYN_SMEM);
        cudaStreamCreateWithFlags(&s1, cudaStreamNonBlocking);
        cudaStreamCreateWithFlags(&s2, cudaStreamNonBlocking);
        cudaEventCreateWithFlags(&evF, cudaEventDisableTiming);
        cudaEventCreateWithFlags(&evW, cudaEventDisableTiming);
        cudaEventCreateWithFlags(&evX, cudaEventDisableTiming);
        cudaEventCreateWithFlags(&evP0, cudaEventDisableTiming);
        cudaEventCreateWithFlags(&evP1, cudaEventDisableTiming);
        cudaEventCreateWithFlags(&evV0, cudaEventDisableTiming);
        cudaEventCreateWithFlags(&evV1, cudaEventDisableTiming);
        cudaEventCreateWithFlags(&evS1, cudaEventDisableTiming);
        init_done = true;
    }

    const dim3 blk(256);
    const float scale = 1.0f / sqrtf((float)DMODEL);
    const int HB = BATCH / 2;   // 4 batches per half
    const int HROWS = HB * SEQ; // 8192 rows per half

    // Per-half offsets
    const long oXp  = (long)HROWS / 128 * 16 * TILE_B / 2;      // bf16 elems: 64*16 panels *8192 elems
    const long oQK  = (long)HB * SEQ * DMODEL * 2;
    const long oVl  = (long)HB * SEQ * DMODEL;                  // linear V hi/lo
    const long oW   = (long)HB * SEQ * SEQ;
    const long oWp  = (long)HB * SEQ * SEQ * 2;
    const long oVt  = (long)HB * DMODEL * SEQ * 2;
    const long oPm  = (long)HB * ICH * SEQ;
    const long oG   = (long)HB * SEQ;
    const long oOut = (long)HB * SEQ * DMODEL;
    const long oAb  = (long)(HROWS / 128) * 16 * TILE_B;        // bytes into x panels

    // ---- Head: split_x (stream 0) || transpose_split_w (s2) ----
    cudaEventRecord(evF, 0);
    cudaStreamWaitEvent(s2, evF, 0);
    cudaStreamWaitEvent(s1, evF, 0);
    split_x<<<(BATCH * SEQ * DMODEL / 4) / 256, blk>>>(x, xp);
    cudaEventRecord(evX, 0);
    {
        dim3 g(16, 16, 3), b(32, 8);
        transpose_split_w<<<g, b, 0, s2>>>(Wq, Wk, Wv, Wtp);
    }
    cudaEventRecord(evW, s2);
    cudaStreamWaitEvent(0, evW, 0);
    cudaStreamWaitEvent(s1, evW, 0);
    cudaStreamWaitEvent(s1, evX, 0);

    dim3 gridP(3 * DMODEL / BN, HROWS / BM, 1);
    dim3 gridS(SEQ / BN, SEQ / BM, HB);
    dim3 gridAV(DMODEL / BN, SEQ / BM, HB);
    dim3 g2(SEQ / 256, HB);
    dim3 g3(SEQ / (256 * 4), SEQ, HB);

    // ---- Half 0 chain on stream 0 ----
    gemm_ps<MODE_PROJ><<<gridP, blk, DYN_SMEM>>>(
        (const char*)xp, (const char*)Wtp, 1.0f, 3 * DMODEL, DMODEL / 32,
        0, 0, 0, nullptr, nullptr, nullptr, bq, bk, bv, Qp, Kp, Vhi, Vlo);
    cudaEventRecord(evP0, 0);
    cudaStreamWaitEvent(s2, evP0, 0);
    {
        dim3 g(DMODEL / 32, SEQ / 32, HB), b(32, 8);
        transpose_v<<<g, b, 0, s2>>>(Vhi, Vlo, Vtp);
    }
    cudaEventRecord(evV0, s2);

    gemm_ps<MODE_SCORES><<<gridS, blk, DYN_SMEM>>>(
        (const char*)Qp, (const char*)Kp, scale, SEQ, DMODEL / 32,
        (long)SEQ * DMODEL * 4, (long)SEQ * DMODEL * 4, (long)SEQ * SEQ,
        weights, pm, ps, nullptr, nullptr, nullptr,
        nullptr, nullptr, nullptr, nullptr);
    sm_pass2<<<g2, blk>>>(pm, ps, gm, gi);
    sm_pass3<<<g3, blk>>>(weights, gm, gi, Wp);
    cudaStreamWaitEvent(0, evV0, 0);
    gemm_ps<MODE_AV><<<gridAV, blk, DYN_SMEM>>>(
        (const char*)Wp, (const char*)Vtp, 1.0f, DMODEL, SEQ / 32,
        (long)SEQ * SEQ * 4, (long)DMODEL * SEQ * 4, (long)SEQ * DMODEL,
        out, nullptr, nullptr, nullptr, nullptr, nullptr,
        nullptr, nullptr, nullptr, nullptr);

    // ---- Half 1 chain on s1 ----
    gemm_ps<MODE_PROJ><<<gridP, blk, DYN_SMEM, s1>>>(
        (const char*)xp + oAb, (const char*)Wtp, 1.0f, 3 * DMODEL, DMODEL / 32,
        0, 0, 0, nullptr, nullptr, nullptr, bq, bk, bv,
        Qp + oQK, Kp + oQK, Vhi + oVl, Vlo + oVl);
    cudaEventRecord(evP1, s1);
    cudaStreamWaitEvent(s2, evP1, 0);
    {
        dim3 g(DMODEL / 32, SEQ / 32, HB), b(32, 8);
        transpose_v<<<g, b, 0, s2>>>(Vhi + oVl, Vlo + oVl, Vtp + oVt);
    }
    cudaEventRecord(evV1, s2);

    gemm_ps<MODE_SCORES><<<gridS, blk, DYN_SMEM, s1>>>(
        (const char*)(Qp + oQK), (const char*)(Kp + oQK), scale, SEQ, DMODEL / 32,
        (long)SEQ * DMODEL * 4, (long)SEQ * DMODEL * 4, (long)SEQ * SEQ,
        weights + oW, pm + oPm, ps + oPm, nullptr, nullptr, nullptr,
        nullptr, nullptr, nullptr, nullptr);
    sm_pass2<<<g2, blk, 0, s1>>>(pm + oPm, ps + oPm, gm + oG, gi + oG);
    sm_pass3<<<g3, blk, 0, s1>>>(weights + oW, gm + oG, gi + oG, Wp + oWp);
    cudaStreamWaitEvent(s1, evV1, 0);
    gemm_ps<MODE_AV><<<gridAV, blk, DYN_SMEM, s1>>>(
        (const char*)(Wp + oWp), (const char*)(Vtp + oVt), 1.0f, DMODEL, SEQ / 32,
        (long)SEQ * SEQ * 4, (long)DMODEL * SEQ * 4, (long)SEQ * DMODEL,
        out + oOut, nullptr, nullptr, nullptr, nullptr, nullptr,
        nullptr, nullptr, nullptr, nullptr);

    // ---- Join ----
    cudaEventRecord(evS1, s1);
    cudaStreamWaitEvent(0, evS1, 0);
}